// round 1
// baseline (speedup 1.0000x reference)
#include <cuda_runtime.h>
#include <cuda_bf16.h>
#include <cstdint>

// Problem constants
#define Bb   4
#define Ss   8192
#define HID  768
#define NH   12
#define HD   64
#define ROWS (Bb*Ss)          // 32768
#define EPS  1e-5f

// ---------------- scratch (device globals; no allocations allowed) ----------
__device__ float g_Q[(size_t)ROWS * HID];
__device__ float g_K[(size_t)ROWS * HID];
__device__ float g_V[(size_t)ROWS * HID];

#define KV_OFF   0                       // 48 * 64 * 64
#define KSUM_OFF (48*4096)               // 48 * 64
#define VSUM_OFF (KSUM_OFF + 48*64)
#define MSUM_OFF (VSUM_OFF + 48*64)
#define RED_TOTAL (MSUM_OFF + 4)
__device__ float g_red[RED_TOTAL];

// ---------------- K0: zero the reduction scratch ----------------------------
__global__ void zero_kernel() {
    int i = blockIdx.x * 256 + threadIdx.x;
    if (i < RED_TOTAL) g_red[i] = 0.0f;
}

// ---------------- K1: fused QKV projection (SGEMM) ---------------------------
// C = X[32768,768] @ W^T, W in {Wq,Wk,Wv}, block tiles 128x128, BK=16,
// 256 threads, 8x8 per-thread microtile. Grid: (18 n-tiles, 256 m-tiles).
__global__ __launch_bounds__(256, 2) void gemm_qkv(
    const float* __restrict__ X,
    const float* __restrict__ Wq, const float* __restrict__ bq,
    const float* __restrict__ Wk, const float* __restrict__ bk,
    const float* __restrict__ Wv, const float* __restrict__ bv)
{
    __shared__ float As[16][128];
    __shared__ float Bs[16][128];

    const int t  = threadIdx.x;
    const int nb = blockIdx.x;          // 0..17
    const int mb = blockIdx.y;          // 0..255
    const int mat = nb / 6;             // 0=q 1=k 2=v
    const float* W    = (mat == 0) ? Wq : (mat == 1) ? Wk : Wv;
    const float* bias = (mat == 0) ? bq : (mat == 1) ? bk : bv;
    float* C          = (mat == 0) ? g_Q : (mat == 1) ? g_K : g_V;
    const int n0 = (nb % 6) * 128;
    const int m0 = mb * 128;

    const int lr = t >> 2;              // 0..63
    const int lk = (t & 3) * 4;         // 0,4,8,12
    const int tx = t & 15;
    const int ty = t >> 4;

    float acc[8][8];
    #pragma unroll
    for (int i = 0; i < 8; i++)
        #pragma unroll
        for (int j = 0; j < 8; j++) acc[i][j] = 0.0f;

    for (int kt = 0; kt < 768; kt += 16) {
        float4 a0 = *(const float4*)&X[(size_t)(m0 + lr)      * 768 + kt + lk];
        float4 a1 = *(const float4*)&X[(size_t)(m0 + lr + 64) * 768 + kt + lk];
        float4 b0 = *(const float4*)&W[(size_t)(n0 + lr)      * 768 + kt + lk];
        float4 b1 = *(const float4*)&W[(size_t)(n0 + lr + 64) * 768 + kt + lk];
        __syncthreads();
        As[lk+0][lr]    = a0.x; As[lk+1][lr]    = a0.y; As[lk+2][lr]    = a0.z; As[lk+3][lr]    = a0.w;
        As[lk+0][lr+64] = a1.x; As[lk+1][lr+64] = a1.y; As[lk+2][lr+64] = a1.z; As[lk+3][lr+64] = a1.w;
        Bs[lk+0][lr]    = b0.x; Bs[lk+1][lr]    = b0.y; Bs[lk+2][lr]    = b0.z; Bs[lk+3][lr]    = b0.w;
        Bs[lk+0][lr+64] = b1.x; Bs[lk+1][lr+64] = b1.y; Bs[lk+2][lr+64] = b1.z; Bs[lk+3][lr+64] = b1.w;
        __syncthreads();
        #pragma unroll
        for (int kk = 0; kk < 16; kk++) {
            float4 av0 = *(float4*)&As[kk][ty*8];
            float4 av1 = *(float4*)&As[kk][ty*8 + 4];
            float4 bv0 = *(float4*)&Bs[kk][tx*8];
            float4 bv1 = *(float4*)&Bs[kk][tx*8 + 4];
            float a_[8] = {av0.x, av0.y, av0.z, av0.w, av1.x, av1.y, av1.z, av1.w};
            float b_[8] = {bv0.x, bv0.y, bv0.z, bv0.w, bv1.x, bv1.y, bv1.z, bv1.w};
            #pragma unroll
            for (int i = 0; i < 8; i++)
                #pragma unroll
                for (int j = 0; j < 8; j++)
                    acc[i][j] = fmaf(a_[i], b_[j], acc[i][j]);
        }
    }

    // epilogue: add bias, store
    float bi[8];
    #pragma unroll
    for (int j = 0; j < 8; j++) bi[j] = bias[n0 + tx*8 + j];
    #pragma unroll
    for (int i = 0; i < 8; i++) {
        size_t r = (size_t)(m0 + ty*8 + i) * 768 + n0 + tx*8;
        float4 v0 = make_float4(acc[i][0]+bi[0], acc[i][1]+bi[1], acc[i][2]+bi[2], acc[i][3]+bi[3]);
        float4 v1 = make_float4(acc[i][4]+bi[4], acc[i][5]+bi[5], acc[i][6]+bi[6], acc[i][7]+bi[7]);
        *(float4*)&C[r]     = v0;
        *(float4*)&C[r + 4] = v1;
    }
}

// ---------------- K2: mask + per-head L2 normalize Q,K (in place) -----------
// one warp per (row, head); lane owns 2 dims
__global__ __launch_bounds__(256) void masknorm_kernel(const float* __restrict__ am) {
    int gw   = (blockIdx.x * 256 + threadIdx.x) >> 5;
    int lane = threadIdx.x & 31;
    int h   = gw % NH;
    int row = gw / NH;                  // b*S + s
    float m = (am[row] != 0.0f) ? 0.0f : 1.0f;
    size_t base = (size_t)row * HID + h * HD + lane * 2;

    float2 q = *(float2*)&g_Q[base];
    q.x *= m; q.y *= m;
    float ssq = q.x*q.x + q.y*q.y;
    #pragma unroll
    for (int o = 16; o; o >>= 1) ssq += __shfl_xor_sync(0xffffffffu, ssq, o);
    float invq = 1.0f / (sqrtf(ssq) + EPS);
    q.x *= invq; q.y *= invq;
    *(float2*)&g_Q[base] = q;

    float2 k = *(float2*)&g_K[base];
    k.x *= m; k.y *= m;
    float ssk = k.x*k.x + k.y*k.y;
    #pragma unroll
    for (int o = 16; o; o >>= 1) ssk += __shfl_xor_sync(0xffffffffu, ssk, o);
    float invk = 1.0f / (sqrtf(ssk) + EPS);
    k.x *= invk; k.y *= invk;
    *(float2*)&g_K[base] = k;
}

// ---------------- K2b: msum per batch ----------------------------------------
__global__ void msum_kernel(const float* __restrict__ am) {
    __shared__ float red[256];
    int b = blockIdx.x;
    float s = 0.0f;
    for (int i = threadIdx.x; i < Ss; i += 256)
        s += (am[b * Ss + i] != 0.0f) ? 0.0f : 1.0f;
    red[threadIdx.x] = s;
    __syncthreads();
    for (int o = 128; o; o >>= 1) {
        if (threadIdx.x < o) red[threadIdx.x] += red[threadIdx.x + o];
        __syncthreads();
    }
    if (threadIdx.x == 0) g_red[MSUM_OFF + b] = red[0];
}

// ---------------- K3: kv = K^T V, ksum, vsum per (b,h) ----------------------
// grid (48, 8): each block handles 1024 s-positions, atomically accumulated
__global__ __launch_bounds__(256) void kv_kernel() {
    int bh = blockIdx.x;
    int b = bh / NH, h = bh % NH;
    int sc = blockIdx.y;

    __shared__ float ks[32][64];
    __shared__ float vs[32][64];

    int t  = threadIdx.x;
    int tx = t & 15, ty = t >> 4;
    float acc[4][4];
    #pragma unroll
    for (int i = 0; i < 4; i++)
        #pragma unroll
        for (int j = 0; j < 4; j++) acc[i][j] = 0.0f;
    float ksum = 0.0f, vsum = 0.0f;

    for (int s0 = sc * 1024; s0 < sc * 1024 + 1024; s0 += 32) {
        __syncthreads();
        #pragma unroll
        for (int p = 0; p < 2; p++) {
            int f = t + p * 256;
            int row = f >> 4, c4 = (f & 15) * 4;
            size_t gi = ((size_t)(b * Ss + s0 + row)) * HID + h * HD + c4;
            *(float4*)&ks[row][c4] = *(const float4*)&g_K[gi];
            *(float4*)&vs[row][c4] = *(const float4*)&g_V[gi];
        }
        __syncthreads();
        #pragma unroll 8
        for (int ss = 0; ss < 32; ss++) {
            float4 ka = *(float4*)&ks[ss][tx*4];
            float4 va = *(float4*)&vs[ss][ty*4];
            float kk[4] = {ka.x, ka.y, ka.z, ka.w};
            float vv[4] = {va.x, va.y, va.z, va.w};
            #pragma unroll
            for (int i = 0; i < 4; i++)
                #pragma unroll
                for (int j = 0; j < 4; j++)
                    acc[i][j] = fmaf(kk[i], vv[j], acc[i][j]);
        }
        if (t < 64)       { for (int ss = 0; ss < 32; ss++) ksum += ks[ss][t]; }
        else if (t < 128) { for (int ss = 0; ss < 32; ss++) vsum += vs[ss][t - 64]; }
    }

    float* kvb = g_red + KV_OFF + bh * 4096;
    #pragma unroll
    for (int i = 0; i < 4; i++)
        #pragma unroll
        for (int j = 0; j < 4; j++)
            atomicAdd(&kvb[(tx*4 + i) * 64 + ty*4 + j], acc[i][j]);
    if (t < 64)       atomicAdd(&g_red[KSUM_OFF + bh * 64 + t], ksum);
    else if (t < 128) atomicAdd(&g_red[VSUM_OFF + bh * 64 + (t - 64)], vsum);
}

// ---------------- K4: out = (q@kv + vsum) / (q.ksum + msum + eps) ------------
// grid (48, 64): block handles 128 s for one (b,h); 4 s-lanes x 64 e-threads
__global__ __launch_bounds__(256) void out_kernel(float* __restrict__ out) {
    int bh = blockIdx.x, st = blockIdx.y;
    int b = bh / NH, h = bh % NH;

    __shared__ float kvs[64][64];
    __shared__ float ksums[64], vsums[64];
    __shared__ float qs[4][64];

    int t = threadIdx.x;
    #pragma unroll
    for (int p = 0; p < 4; p++) {
        int f = t + p * 256;   // float4 index, 1024 total
        ((float4*)kvs)[f] = ((const float4*)(g_red + KV_OFF + (size_t)bh * 4096))[f];
    }
    if (t < 64)       ksums[t]      = g_red[KSUM_OFF + bh * 64 + t];
    else if (t < 128) vsums[t - 64] = g_red[VSUM_OFF + bh * 64 + (t - 64)];
    float msum = g_red[MSUM_OFF + b];
    __syncthreads();

    int g = t >> 6, e = t & 63;
    for (int it = 0; it < 32; it++) {
        int s = st * 128 + it * 4 + g;
        size_t base = ((size_t)(b * Ss + s)) * HID + h * HD;
        qs[g][e] = g_Q[base + e];
        __syncthreads();
        float ctx = vsums[e];
        float nq  = 0.0f;
        #pragma unroll
        for (int d = 0; d < 64; d++) {
            float qd = qs[g][d];
            ctx = fmaf(qd, kvs[d][e], ctx);
            nq  = fmaf(qd, ksums[d], nq);
        }
        out[base + e] = ctx / (nq + EPS + msum);
        __syncthreads();
    }
}

// ---------------- launch ------------------------------------------------------
extern "C" void kernel_launch(void* const* d_in, const int* in_sizes, int n_in,
                              void* d_out, int out_size)
{
    const float* X  = (const float*)d_in[0];   // hidden_states [4,8192,768]
    const float* am = (const float*)d_in[1];   // attention_mask [4,1,1,8192]
    const float* Wq = (const float*)d_in[2];
    const float* bq = (const float*)d_in[3];
    const float* Wk = (const float*)d_in[4];
    const float* bk = (const float*)d_in[5];
    const float* Wv = (const float*)d_in[6];
    const float* bv = (const float*)d_in[7];
    float* out = (float*)d_out;

    zero_kernel<<<(RED_TOTAL + 255) / 256, 256>>>();

    dim3 g1(18, 256);
    gemm_qkv<<<g1, 256>>>(X, Wq, bq, Wk, bk, Wv, bv);

    masknorm_kernel<<<(ROWS * NH) / 8, 256>>>(am);
    msum_kernel<<<Bb, 256>>>(am);

    dim3 g3(48, 8);
    kv_kernel<<<g3, 256>>>();

    dim3 g4(48, 64);
    out_kernel<<<g4, 256>>>(out);
}

// round 3
// speedup vs baseline: 2.2444x; 2.2444x over previous
#include <cuda_runtime.h>
#include <cuda_bf16.h>
#include <cstdint>

// Problem constants
#define Bb   4
#define Ss   8192
#define HID  768
#define NH   12
#define HD   64
#define ROWS (Bb*Ss)          // 32768
#define EPS  1e-5f

// ---------------- scratch (device globals; no allocations allowed) ----------
__device__ float g_Q[(size_t)ROWS * HID];
__device__ float g_K[(size_t)ROWS * HID];
__device__ float g_V[(size_t)ROWS * HID];

#define KV_OFF   0                       // 48 * 64 * 64
#define KSUM_OFF (48*4096)               // 48 * 64
#define VSUM_OFF (KSUM_OFF + 48*64)
#define MSUM_OFF (VSUM_OFF + 48*64)
#define RED_TOTAL (MSUM_OFF + 4)
__device__ float g_red[RED_TOTAL];

// ---------------- K0: zero the reduction scratch ----------------------------
__global__ void zero_kernel() {
    int i = blockIdx.x * 256 + threadIdx.x;
    if (i < RED_TOTAL) g_red[i] = 0.0f;
}

// ================= helpers ====================================================
__device__ __forceinline__ uint32_t smem_u32(const void* p) {
    uint32_t a;
    asm("{ .reg .u64 t; cvta.to.shared.u64 t, %1; cvt.u32.u64 %0, t; }" : "=r"(a) : "l"(p));
    return a;
}
#define CP_ASYNC16(dst, src) \
    asm volatile("cp.async.cg.shared.global [%0], [%1], 16;" :: "r"((uint32_t)(dst)), "l"(src) : "memory")
#define CP_COMMIT() asm volatile("cp.async.commit_group;" ::: "memory")

__device__ __forceinline__ uint32_t f2tf32(float f) {
    uint32_t r;
    asm("cvt.rna.tf32.f32 %0, %1;" : "=r"(r) : "f"(f));
    return r;
}
__device__ __forceinline__ void mma_tf32(float* d, const uint32_t* a, const uint32_t* b) {
    asm volatile(
        "mma.sync.aligned.m16n8k8.row.col.f32.tf32.tf32.f32 "
        "{%0,%1,%2,%3}, {%4,%5,%6,%7}, {%8,%9}, {%0,%1,%2,%3};"
        : "+f"(d[0]), "+f"(d[1]), "+f"(d[2]), "+f"(d[3])
        : "r"(a[0]), "r"(a[1]), "r"(a[2]), "r"(a[3]), "r"(b[0]), "r"(b[1]));
}

// ---------------- K1: fused QKV projection, tf32 mma.sync --------------------
// C = X[32768,768] @ W^T, 128x128x16 CTA tile, 8 warps (2m x 4n), 64x32 warp
// tile of m16n8k8 fragments. Double-buffered cp.async staging.
// Grid (18, 256): x = n-tile over [Wq|Wk|Wv] (6 tiles of 128 each), y = m-tile.
#define LDA 20   // padded row length (floats): 16 data + 4 pad, 80B (16B aligned)

__global__ void __launch_bounds__(256) gemm_qkv_mma(
    const float* __restrict__ X,
    const float* __restrict__ Wq, const float* __restrict__ bq,
    const float* __restrict__ Wk, const float* __restrict__ bk,
    const float* __restrict__ Wv, const float* __restrict__ bv)
{
    __shared__ float As[2][128 * LDA];
    __shared__ float Bs[2][128 * LDA];

    const int t    = threadIdx.x;
    const int wid  = t >> 5, lane = t & 31;
    const int wm   = wid & 1,  wn  = wid >> 1;
    const int grp  = lane >> 2, tig = lane & 3;

    const int nb = blockIdx.x;          // 0..17
    const int mb = blockIdx.y;          // 0..255
    const int mat = nb / 6;             // 0=q 1=k 2=v
    const float* W    = (mat == 0) ? Wq : (mat == 1) ? Wk : Wv;
    const float* bias = (mat == 0) ? bq : (mat == 1) ? bk : bv;
    float* C          = (mat == 0) ? g_Q : (mat == 1) ? g_K : g_V;
    const int n0 = (nb % 6) * 128;
    const int m0 = mb * 128;

    const uint32_t sA = smem_u32(As);
    const uint32_t sB = smem_u32(Bs);

    // loader: tile 128 rows x 16 k-floats; 512 float4s per matrix, 2/thread
    const int lrow = t >> 2;            // 0..63  (x4 via +64 offsets? no: s-scheme)
    auto load_tile = [&](int kt, int buf) {
        #pragma unroll
        for (int i = 0; i < 2; i++) {
            int s   = t + i * 256;      // 0..511
            int row = s >> 2, c = s & 3;
            uint32_t doff = (uint32_t)(buf * 128 * LDA + row * LDA + c * 4) * 4u;
            CP_ASYNC16(sA + doff, X + (size_t)(m0 + row) * 768 + kt * 16 + c * 4);
            CP_ASYNC16(sB + doff, W + (size_t)(n0 + row) * 768 + kt * 16 + c * 4);
        }
        CP_COMMIT();
    };
    (void)lrow;

    float acc[4][4][4];
    #pragma unroll
    for (int i = 0; i < 4; i++)
        #pragma unroll
        for (int j = 0; j < 4; j++)
            #pragma unroll
            for (int c = 0; c < 4; c++) acc[i][j][c] = 0.0f;

    load_tile(0, 0);

    for (int kt = 0; kt < 48; kt++) {
        const int buf = kt & 1;
        if (kt + 1 < 48) {
            load_tile(kt + 1, buf ^ 1);
            asm volatile("cp.async.wait_group 1;" ::: "memory");
        } else {
            asm volatile("cp.async.wait_group 0;" ::: "memory");
        }
        __syncthreads();

        const float* Ab = As[buf];
        const float* Bt = Bs[buf];
        #pragma unroll
        for (int ks = 0; ks < 2; ks++) {
            const int k0 = ks * 8;
            uint32_t afr[4][4];
            #pragma unroll
            for (int mt = 0; mt < 4; mt++) {
                int m = wm * 64 + mt * 16;
                afr[mt][0] = f2tf32(Ab[(m + grp)     * LDA + k0 + tig]);
                afr[mt][1] = f2tf32(Ab[(m + grp + 8) * LDA + k0 + tig]);
                afr[mt][2] = f2tf32(Ab[(m + grp)     * LDA + k0 + tig + 4]);
                afr[mt][3] = f2tf32(Ab[(m + grp + 8) * LDA + k0 + tig + 4]);
            }
            uint32_t bfr[4][2];
            #pragma unroll
            for (int nt = 0; nt < 4; nt++) {
                int n = wn * 32 + nt * 8;
                bfr[nt][0] = f2tf32(Bt[(n + grp) * LDA + k0 + tig]);
                bfr[nt][1] = f2tf32(Bt[(n + grp) * LDA + k0 + tig + 4]);
            }
            #pragma unroll
            for (int mt = 0; mt < 4; mt++)
                #pragma unroll
                for (int nt = 0; nt < 4; nt++)
                    mma_tf32(acc[mt][nt], afr[mt], bfr[nt]);
        }
        __syncthreads();
    }

    // epilogue: add bias, store float2 per fragment row
    const int rbase = m0 + wm * 64;
    const int cbase = n0 + wn * 32;
    #pragma unroll
    for (int nt = 0; nt < 4; nt++) {
        int col = cbase + nt * 8 + tig * 2;
        float bx = bias[col], by = bias[col + 1];
        #pragma unroll
        for (int mt = 0; mt < 4; mt++) {
            size_t r0 = (size_t)(rbase + mt * 16 + grp) * 768 + col;
            float2 v0 = make_float2(acc[mt][nt][0] + bx, acc[mt][nt][1] + by);
            float2 v1 = make_float2(acc[mt][nt][2] + bx, acc[mt][nt][3] + by);
            *(float2*)&C[r0]            = v0;
            *(float2*)&C[r0 + 8 * 768]  = v1;
        }
    }
}

// ---------------- K2: mask + per-head L2 normalize Q,K (in place) -----------
__global__ __launch_bounds__(256) void masknorm_kernel(const float* __restrict__ am) {
    int gw   = (blockIdx.x * 256 + threadIdx.x) >> 5;
    int lane = threadIdx.x & 31;
    int h   = gw % NH;
    int row = gw / NH;                  // b*S + s
    float m = (am[row] != 0.0f) ? 0.0f : 1.0f;
    size_t base = (size_t)row * HID + h * HD + lane * 2;

    float2 q = *(float2*)&g_Q[base];
    q.x *= m; q.y *= m;
    float ssq = q.x*q.x + q.y*q.y;
    #pragma unroll
    for (int o = 16; o; o >>= 1) ssq += __shfl_xor_sync(0xffffffffu, ssq, o);
    float invq = 1.0f / (sqrtf(ssq) + EPS);
    q.x *= invq; q.y *= invq;
    *(float2*)&g_Q[base] = q;

    float2 k = *(float2*)&g_K[base];
    k.x *= m; k.y *= m;
    float ssk = k.x*k.x + k.y*k.y;
    #pragma unroll
    for (int o = 16; o; o >>= 1) ssk += __shfl_xor_sync(0xffffffffu, ssk, o);
    float invk = 1.0f / (sqrtf(ssk) + EPS);
    k.x *= invk; k.y *= invk;
    *(float2*)&g_K[base] = k;
}

// ---------------- K2b: msum per batch ----------------------------------------
__global__ void msum_kernel(const float* __restrict__ am) {
    __shared__ float red[256];
    int b = blockIdx.x;
    float s = 0.0f;
    for (int i = threadIdx.x; i < Ss; i += 256)
        s += (am[b * Ss + i] != 0.0f) ? 0.0f : 1.0f;
    red[threadIdx.x] = s;
    __syncthreads();
    for (int o = 128; o; o >>= 1) {
        if (threadIdx.x < o) red[threadIdx.x] += red[threadIdx.x + o];
        __syncthreads();
    }
    if (threadIdx.x == 0) g_red[MSUM_OFF + b] = red[0];
}

// ---------------- K3: kv = K^T V, ksum, vsum per (b,h) ----------------------
__global__ __launch_bounds__(256) void kv_kernel() {
    int bh = blockIdx.x;
    int b = bh / NH, h = bh % NH;
    int sc = blockIdx.y;

    __shared__ float ks[32][64];
    __shared__ float vs[32][64];

    int t  = threadIdx.x;
    int tx = t & 15, ty = t >> 4;
    float acc[4][4];
    #pragma unroll
    for (int i = 0; i < 4; i++)
        #pragma unroll
        for (int j = 0; j < 4; j++) acc[i][j] = 0.0f;
    float ksum = 0.0f, vsum = 0.0f;

    for (int s0 = sc * 1024; s0 < sc * 1024 + 1024; s0 += 32) {
        __syncthreads();
        #pragma unroll
        for (int p = 0; p < 2; p++) {
            int f = t + p * 256;
            int row = f >> 4, c4 = (f & 15) * 4;
            size_t gi = ((size_t)(b * Ss + s0 + row)) * HID + h * HD + c4;
            *(float4*)&ks[row][c4] = *(const float4*)&g_K[gi];
            *(float4*)&vs[row][c4] = *(const float4*)&g_V[gi];
        }
        __syncthreads();
        #pragma unroll 8
        for (int ss = 0; ss < 32; ss++) {
            float4 ka = *(float4*)&ks[ss][tx*4];
            float4 va = *(float4*)&vs[ss][ty*4];
            float kk[4] = {ka.x, ka.y, ka.z, ka.w};
            float vv[4] = {va.x, va.y, va.z, va.w};
            #pragma unroll
            for (int i = 0; i < 4; i++)
                #pragma unroll
                for (int j = 0; j < 4; j++)
                    acc[i][j] = fmaf(kk[i], vv[j], acc[i][j]);
        }
        if (t < 64)       { for (int ss = 0; ss < 32; ss++) ksum += ks[ss][t]; }
        else if (t < 128) { for (int ss = 0; ss < 32; ss++) vsum += vs[ss][t - 64]; }
    }

    float* kvb = g_red + KV_OFF + bh * 4096;
    #pragma unroll
    for (int i = 0; i < 4; i++)
        #pragma unroll
        for (int j = 0; j < 4; j++)
            atomicAdd(&kvb[(tx*4 + i) * 64 + ty*4 + j], acc[i][j]);
    if (t < 64)       atomicAdd(&g_red[KSUM_OFF + bh * 64 + t], ksum);
    else if (t < 128) atomicAdd(&g_red[VSUM_OFF + bh * 64 + (t - 64)], vsum);
}

// ---------------- K4: out = (q@kv + vsum) / (q.ksum + msum + eps) ------------
__global__ __launch_bounds__(256) void out_kernel(float* __restrict__ out) {
    int bh = blockIdx.x, st = blockIdx.y;
    int b = bh / NH, h = bh % NH;

    __shared__ float kvs[64][64];
    __shared__ float ksums[64], vsums[64];
    __shared__ float qs[4][64];

    int t = threadIdx.x;
    #pragma unroll
    for (int p = 0; p < 4; p++) {
        int f = t + p * 256;
        ((float4*)kvs)[f] = ((const float4*)(g_red + KV_OFF + (size_t)bh * 4096))[f];
    }
    if (t < 64)       ksums[t]      = g_red[KSUM_OFF + bh * 64 + t];
    else if (t < 128) vsums[t - 64] = g_red[VSUM_OFF + bh * 64 + (t - 64)];
    float msum = g_red[MSUM_OFF + b];
    __syncthreads();

    int g = t >> 6, e = t & 63;
    for (int it = 0; it < 32; it++) {
        int s = st * 128 + it * 4 + g;
        size_t base = ((size_t)(b * Ss + s)) * HID + h * HD;
        qs[g][e] = g_Q[base + e];
        __syncthreads();
        float ctx = vsums[e];
        float nq  = 0.0f;
        #pragma unroll
        for (int d = 0; d < 64; d++) {
            float qd = qs[g][d];
            ctx = fmaf(qd, kvs[d][e], ctx);
            nq  = fmaf(qd, ksums[d], nq);
        }
        out[base + e] = ctx / (nq + EPS + msum);
        __syncthreads();
    }
}

// ---------------- launch ------------------------------------------------------
extern "C" void kernel_launch(void* const* d_in, const int* in_sizes, int n_in,
                              void* d_out, int out_size)
{
    const float* X  = (const float*)d_in[0];
    const float* am = (const float*)d_in[1];
    const float* Wq = (const float*)d_in[2];
    const float* bq = (const float*)d_in[3];
    const float* Wk = (const float*)d_in[4];
    const float* bk = (const float*)d_in[5];
    const float* Wv = (const float*)d_in[6];
    const float* bv = (const float*)d_in[7];
    float* out = (float*)d_out;

    zero_kernel<<<(RED_TOTAL + 255) / 256, 256>>>();
    msum_kernel<<<Bb, 256>>>(am);

    dim3 g1(18, 256);
    gemm_qkv_mma<<<g1, 256>>>(X, Wq, bq, Wk, bk, Wv, bv);

    masknorm_kernel<<<(ROWS * NH) / 8, 256>>>(am);

    dim3 g3(48, 8);
    kv_kernel<<<g3, 256>>>();

    dim3 g4(48, 64);
    out_kernel<<<g4, 256>>>(out);
}

// round 4
// speedup vs baseline: 2.9431x; 1.3113x over previous
#include <cuda_runtime.h>
#include <cuda_bf16.h>
#include <cstdint>

// Problem constants
#define Bb   4
#define Ss   8192
#define HID  768
#define NH   12
#define HD   64
#define ROWS (Bb*Ss)          // 32768
#define EPS  1e-5f

// ---------------- scratch (device globals; no allocations allowed) ----------
__device__ float g_Q[(size_t)ROWS * HID];
__device__ float g_K[(size_t)ROWS * HID];
__device__ float g_V[(size_t)ROWS * HID];

#define KV_OFF   0                       // 48 * 64 * 64
#define KSUM_OFF (48*4096)               // 48 * 64
#define VSUM_OFF (KSUM_OFF + 48*64)
#define MSUM_OFF (VSUM_OFF + 48*64)
#define RED_TOTAL (MSUM_OFF + 4)
__device__ float g_red[RED_TOTAL];

// ---------------- K0: zero the reduction scratch ----------------------------
__global__ void zero_kernel() {
    int i = blockIdx.x * 256 + threadIdx.x;
    if (i < RED_TOTAL) g_red[i] = 0.0f;
}

// ================= helpers ====================================================
__device__ __forceinline__ uint32_t smem_u32(const void* p) {
    uint32_t a;
    asm("{ .reg .u64 t; cvta.to.shared.u64 t, %1; cvt.u32.u64 %0, t; }" : "=r"(a) : "l"(p));
    return a;
}
#define CP_ASYNC16(dst, src) \
    asm volatile("cp.async.cg.shared.global [%0], [%1], 16;" :: "r"((uint32_t)(dst)), "l"(src) : "memory")
#define CP_COMMIT() asm volatile("cp.async.commit_group;" ::: "memory")

__device__ __forceinline__ uint32_t f2tf32(float f) {
    uint32_t r;
    asm("cvt.rna.tf32.f32 %0, %1;" : "=r"(r) : "f"(f));
    return r;
}
__device__ __forceinline__ void mma_tf32(float* d, const uint32_t* a, const uint32_t* b) {
    asm volatile(
        "mma.sync.aligned.m16n8k8.row.col.f32.tf32.tf32.f32 "
        "{%0,%1,%2,%3}, {%4,%5,%6,%7}, {%8,%9}, {%0,%1,%2,%3};"
        : "+f"(d[0]), "+f"(d[1]), "+f"(d[2]), "+f"(d[3])
        : "r"(a[0]), "r"(a[1]), "r"(a[2]), "r"(a[3]), "r"(b[0]), "r"(b[1]));
}

// ---------------- K1: fused QKV projection + mask + L2-norm ------------------
// C = X[32768,768] @ W^T, 128x128x16 CTA tile, 8 warps (2m x 4n), 64x32 warp
// tile of m16n8k8 fragments. Epilogue: for Q,K apply row mask, per-(row,head)
// L2 normalization (a 128-col n-tile spans exactly 2 heads).
// Grid (18, 256): x = n-tile over [Wq|Wk|Wv] (6 tiles of 128 each), y = m-tile.
#define LDA 20   // padded row length (floats)

__global__ void __launch_bounds__(256) gemm_qkv_mma(
    const float* __restrict__ X, const float* __restrict__ am,
    const float* __restrict__ Wq, const float* __restrict__ bq,
    const float* __restrict__ Wk, const float* __restrict__ bk,
    const float* __restrict__ Wv, const float* __restrict__ bv)
{
    __shared__ float As[2][128 * LDA];
    __shared__ float Bs[2][128 * LDA];
    __shared__ float ssqs[128][2];

    const int t    = threadIdx.x;
    const int wid  = t >> 5, lane = t & 31;
    const int wm   = wid & 1,  wn  = wid >> 1;
    const int grp  = lane >> 2, tig = lane & 3;

    const int nb = blockIdx.x;          // 0..17
    const int mb = blockIdx.y;          // 0..255
    const int mat = nb / 6;             // 0=q 1=k 2=v
    const float* W    = (mat == 0) ? Wq : (mat == 1) ? Wk : Wv;
    const float* bias = (mat == 0) ? bq : (mat == 1) ? bk : bv;
    float* C          = (mat == 0) ? g_Q : (mat == 1) ? g_K : g_V;
    const int n0 = (nb % 6) * 128;
    const int m0 = mb * 128;

    const uint32_t sA = smem_u32(As);
    const uint32_t sB = smem_u32(Bs);

    auto load_tile = [&](int kt, int buf) {
        #pragma unroll
        for (int i = 0; i < 2; i++) {
            int s   = t + i * 256;      // 0..511
            int row = s >> 2, c = s & 3;
            uint32_t doff = (uint32_t)(buf * 128 * LDA + row * LDA + c * 4) * 4u;
            CP_ASYNC16(sA + doff, X + (size_t)(m0 + row) * 768 + kt * 16 + c * 4);
            CP_ASYNC16(sB + doff, W + (size_t)(n0 + row) * 768 + kt * 16 + c * 4);
        }
        CP_COMMIT();
    };

    float acc[4][4][4];
    #pragma unroll
    for (int i = 0; i < 4; i++)
        #pragma unroll
        for (int j = 0; j < 4; j++)
            #pragma unroll
            for (int c = 0; c < 4; c++) acc[i][j][c] = 0.0f;

    load_tile(0, 0);

    for (int kt = 0; kt < 48; kt++) {
        const int buf = kt & 1;
        if (kt + 1 < 48) {
            load_tile(kt + 1, buf ^ 1);
            asm volatile("cp.async.wait_group 1;" ::: "memory");
        } else {
            asm volatile("cp.async.wait_group 0;" ::: "memory");
        }
        __syncthreads();

        const float* Ab = As[buf];
        const float* Bt = Bs[buf];
        #pragma unroll
        for (int ks = 0; ks < 2; ks++) {
            const int k0 = ks * 8;
            uint32_t afr[4][4];
            #pragma unroll
            for (int mt = 0; mt < 4; mt++) {
                int m = wm * 64 + mt * 16;
                afr[mt][0] = f2tf32(Ab[(m + grp)     * LDA + k0 + tig]);
                afr[mt][1] = f2tf32(Ab[(m + grp + 8) * LDA + k0 + tig]);
                afr[mt][2] = f2tf32(Ab[(m + grp)     * LDA + k0 + tig + 4]);
                afr[mt][3] = f2tf32(Ab[(m + grp + 8) * LDA + k0 + tig + 4]);
            }
            uint32_t bfr[4][2];
            #pragma unroll
            for (int nt = 0; nt < 4; nt++) {
                int n = wn * 32 + nt * 8;
                bfr[nt][0] = f2tf32(Bt[(n + grp) * LDA + k0 + tig]);
                bfr[nt][1] = f2tf32(Bt[(n + grp) * LDA + k0 + tig + 4]);
            }
            #pragma unroll
            for (int mt = 0; mt < 4; mt++)
                #pragma unroll
                for (int nt = 0; nt < 4; nt++)
                    mma_tf32(acc[mt][nt], afr[mt], bfr[nt]);
        }
        __syncthreads();
    }

    // -------- epilogue --------
    const int rbase = m0 + wm * 64;
    const int cbase = n0 + wn * 32;
    const int head  = wn >> 1;          // which of the 2 heads in this n-tile

    if (mat < 2) {
        // bias + mask, accumulate per-(row,head) sum of squares
        ssqs[t >> 1][t & 1] = 0.0f;
        __syncthreads();

        float mrow[4][2];
        #pragma unroll
        for (int mt = 0; mt < 4; mt++) {
            mrow[mt][0] = (am[m0 + wm*64 + mt*16 + grp]     != 0.0f) ? 0.0f : 1.0f;
            mrow[mt][1] = (am[m0 + wm*64 + mt*16 + grp + 8] != 0.0f) ? 0.0f : 1.0f;
        }
        float part[4][2];
        #pragma unroll
        for (int mt = 0; mt < 4; mt++) { part[mt][0] = 0.0f; part[mt][1] = 0.0f; }

        #pragma unroll
        for (int nt = 0; nt < 4; nt++) {
            int col = cbase + nt * 8 + tig * 2;
            float bx = bias[col], by = bias[col + 1];
            #pragma unroll
            for (int mt = 0; mt < 4; mt++) {
                float a0 = (acc[mt][nt][0] + bx) * mrow[mt][0];
                float a1 = (acc[mt][nt][1] + by) * mrow[mt][0];
                float a2 = (acc[mt][nt][2] + bx) * mrow[mt][1];
                float a3 = (acc[mt][nt][3] + by) * mrow[mt][1];
                acc[mt][nt][0] = a0; acc[mt][nt][1] = a1;
                acc[mt][nt][2] = a2; acc[mt][nt][3] = a3;
                part[mt][0] += a0*a0 + a1*a1;
                part[mt][1] += a2*a2 + a3*a3;
            }
        }
        // reduce over tig (quad)
        #pragma unroll
        for (int off = 1; off <= 2; off <<= 1)
            #pragma unroll
            for (int mt = 0; mt < 4; mt++) {
                part[mt][0] += __shfl_xor_sync(0xffffffffu, part[mt][0], off);
                part[mt][1] += __shfl_xor_sync(0xffffffffu, part[mt][1], off);
            }
        if (tig == 0) {
            #pragma unroll
            for (int mt = 0; mt < 4; mt++) {
                atomicAdd(&ssqs[wm*64 + mt*16 + grp][head],     part[mt][0]);
                atomicAdd(&ssqs[wm*64 + mt*16 + grp + 8][head], part[mt][1]);
            }
        }
        __syncthreads();

        float inv[4][2];
        #pragma unroll
        for (int mt = 0; mt < 4; mt++) {
            inv[mt][0] = 1.0f / (sqrtf(ssqs[wm*64 + mt*16 + grp][head])     + EPS);
            inv[mt][1] = 1.0f / (sqrtf(ssqs[wm*64 + mt*16 + grp + 8][head]) + EPS);
        }
        #pragma unroll
        for (int nt = 0; nt < 4; nt++) {
            int col = cbase + nt * 8 + tig * 2;
            #pragma unroll
            for (int mt = 0; mt < 4; mt++) {
                size_t r0 = (size_t)(rbase + mt * 16 + grp) * 768 + col;
                float2 v0 = make_float2(acc[mt][nt][0] * inv[mt][0], acc[mt][nt][1] * inv[mt][0]);
                float2 v1 = make_float2(acc[mt][nt][2] * inv[mt][1], acc[mt][nt][3] * inv[mt][1]);
                *(float2*)&C[r0]           = v0;
                *(float2*)&C[r0 + 8 * 768] = v1;
            }
        }
    } else {
        // V: bias only
        #pragma unroll
        for (int nt = 0; nt < 4; nt++) {
            int col = cbase + nt * 8 + tig * 2;
            float bx = bias[col], by = bias[col + 1];
            #pragma unroll
            for (int mt = 0; mt < 4; mt++) {
                size_t r0 = (size_t)(rbase + mt * 16 + grp) * 768 + col;
                float2 v0 = make_float2(acc[mt][nt][0] + bx, acc[mt][nt][1] + by);
                float2 v1 = make_float2(acc[mt][nt][2] + bx, acc[mt][nt][3] + by);
                *(float2*)&C[r0]           = v0;
                *(float2*)&C[r0 + 8 * 768] = v1;
            }
        }
    }
}

// ---------------- K2b: msum per batch ----------------------------------------
__global__ void msum_kernel(const float* __restrict__ am) {
    __shared__ float red[256];
    int b = blockIdx.x;
    float s = 0.0f;
    for (int i = threadIdx.x; i < Ss; i += 256)
        s += (am[b * Ss + i] != 0.0f) ? 0.0f : 1.0f;
    red[threadIdx.x] = s;
    __syncthreads();
    for (int o = 128; o; o >>= 1) {
        if (threadIdx.x < o) red[threadIdx.x] += red[threadIdx.x + o];
        __syncthreads();
    }
    if (threadIdx.x == 0) g_red[MSUM_OFF + b] = red[0];
}

// ---------------- K3: kv = K^T V, ksum, vsum per (b,h) ----------------------
__global__ __launch_bounds__(256) void kv_kernel() {
    int bh = blockIdx.x;
    int b = bh / NH, h = bh % NH;
    int sc = blockIdx.y;

    __shared__ float ks[32][64];
    __shared__ float vs[32][64];

    int t  = threadIdx.x;
    int tx = t & 15, ty = t >> 4;
    float acc[4][4];
    #pragma unroll
    for (int i = 0; i < 4; i++)
        #pragma unroll
        for (int j = 0; j < 4; j++) acc[i][j] = 0.0f;
    float ksum = 0.0f, vsum = 0.0f;

    for (int s0 = sc * 1024; s0 < sc * 1024 + 1024; s0 += 32) {
        __syncthreads();
        #pragma unroll
        for (int p = 0; p < 2; p++) {
            int f = t + p * 256;
            int row = f >> 4, c4 = (f & 15) * 4;
            size_t gi = ((size_t)(b * Ss + s0 + row)) * HID + h * HD + c4;
            *(float4*)&ks[row][c4] = *(const float4*)&g_K[gi];
            *(float4*)&vs[row][c4] = *(const float4*)&g_V[gi];
        }
        __syncthreads();
        #pragma unroll 8
        for (int ss = 0; ss < 32; ss++) {
            float4 ka = *(float4*)&ks[ss][tx*4];
            float4 va = *(float4*)&vs[ss][ty*4];
            float kk[4] = {ka.x, ka.y, ka.z, ka.w};
            float vv[4] = {va.x, va.y, va.z, va.w};
            #pragma unroll
            for (int i = 0; i < 4; i++)
                #pragma unroll
                for (int j = 0; j < 4; j++)
                    acc[i][j] = fmaf(kk[i], vv[j], acc[i][j]);
        }
        if (t < 64)       { for (int ss = 0; ss < 32; ss++) ksum += ks[ss][t]; }
        else if (t < 128) { for (int ss = 0; ss < 32; ss++) vsum += vs[ss][t - 64]; }
    }

    float* kvb = g_red + KV_OFF + bh * 4096;
    #pragma unroll
    for (int i = 0; i < 4; i++)
        #pragma unroll
        for (int j = 0; j < 4; j++)
            atomicAdd(&kvb[(tx*4 + i) * 64 + ty*4 + j], acc[i][j]);
    if (t < 64)       atomicAdd(&g_red[KSUM_OFF + bh * 64 + t], ksum);
    else if (t < 128) atomicAdd(&g_red[VSUM_OFF + bh * 64 + (t - 64)], vsum);
}

// ---------------- K4: out via tensor cores -----------------------------------
// Per CTA (bh, st): C[128 s][72] = Q[128][64] @ kvT^T, where kvT[n][k]:
// n<64 -> kv[k][n], n==64 -> ksum[k], n>64 -> 0. Output col 64 = nq.
// out[s][e] = (C[s][e] + vsum[e]) / (C[s][64] + msum + eps).
// 128 threads = 4 warps, warp handles 32 rows (2 m16 tiles), 9 n-tiles of 8.
#define QP 68   // Q smem row pitch (floats)
#define OUT_SMEM ((128*QP + 72*QP + 128 + 64) * 4)

__global__ void __launch_bounds__(128) out_mma(float* __restrict__ out) {
    extern __shared__ float sm[];
    float* Qs  = sm;                 // [128][QP]
    float* kvT = sm + 128 * QP;      // [72][QP]
    float* nqs = kvT + 72 * QP;      // [128]
    float* vs  = nqs + 128;          // [64]

    const int bh = blockIdx.x, st = blockIdx.y;
    const int b = bh / NH, h = bh % NH;
    const int t = threadIdx.x;
    const int wid = t >> 5, lane = t & 31;
    const int grp = lane >> 2, tig = lane & 3;

    // load Q tile via cp.async: 128 rows x 16 float4
    const uint32_t sQ = smem_u32(Qs);
    #pragma unroll
    for (int i = 0; i < 16; i++) {
        int s = t + i * 128;         // 0..2047
        int row = s >> 4, c = s & 15;
        CP_ASYNC16(sQ + (uint32_t)(row * QP + c * 4) * 4u,
                   g_Q + ((size_t)(b * Ss + st * 128 + row)) * HID + h * HD + c * 4);
    }
    CP_COMMIT();

    // load kvT (transposed kv + ksum row + zero rows)
    for (int idx = t; idx < 72 * 64; idx += 128) {
        int n = idx >> 6, k = idx & 63;
        float v;
        if (n < 64)       v = g_red[KV_OFF + bh * 4096 + k * 64 + n];
        else if (n == 64) v = g_red[KSUM_OFF + bh * 64 + k];
        else              v = 0.0f;
        kvT[n * QP + k] = v;
    }
    if (t < 64) vs[t] = g_red[VSUM_OFF + bh * 64 + t];
    const float msum = g_red[MSUM_OFF + b];

    asm volatile("cp.async.wait_group 0;" ::: "memory");
    __syncthreads();

    float acc[2][9][4];
    #pragma unroll
    for (int i = 0; i < 2; i++)
        #pragma unroll
        for (int j = 0; j < 9; j++)
            #pragma unroll
            for (int c = 0; c < 4; c++) acc[i][j][c] = 0.0f;

    #pragma unroll
    for (int ks = 0; ks < 8; ks++) {
        const int k0 = ks * 8;
        uint32_t afr[2][4];
        #pragma unroll
        for (int mt = 0; mt < 2; mt++) {
            int m = wid * 32 + mt * 16;
            afr[mt][0] = f2tf32(Qs[(m + grp)     * QP + k0 + tig]);
            afr[mt][1] = f2tf32(Qs[(m + grp + 8) * QP + k0 + tig]);
            afr[mt][2] = f2tf32(Qs[(m + grp)     * QP + k0 + tig + 4]);
            afr[mt][3] = f2tf32(Qs[(m + grp + 8) * QP + k0 + tig + 4]);
        }
        #pragma unroll
        for (int nt = 0; nt < 9; nt++) {
            uint32_t bfr[2];
            bfr[0] = f2tf32(kvT[(nt * 8 + grp) * QP + k0 + tig]);
            bfr[1] = f2tf32(kvT[(nt * 8 + grp) * QP + k0 + tig + 4]);
            #pragma unroll
            for (int mt = 0; mt < 2; mt++)
                mma_tf32(acc[mt][nt], afr[mt], bfr);
        }
    }

    // publish nq (output col 64 = n-tile 8, within-tile col 0 -> tig==0, c0/c2)
    if (tig == 0) {
        #pragma unroll
        for (int mt = 0; mt < 2; mt++) {
            nqs[wid * 32 + mt * 16 + grp]     = acc[mt][8][0];
            nqs[wid * 32 + mt * 16 + grp + 8] = acc[mt][8][2];
        }
    }
    __syncthreads();

    #pragma unroll
    for (int mt = 0; mt < 2; mt++) {
        int r0 = wid * 32 + mt * 16 + grp;
        float inv0 = 1.0f / (nqs[r0]     + EPS + msum);
        float inv1 = 1.0f / (nqs[r0 + 8] + EPS + msum);
        size_t g0 = ((size_t)(b * Ss + st * 128 + r0))     * HID + h * HD;
        size_t g1 = ((size_t)(b * Ss + st * 128 + r0 + 8)) * HID + h * HD;
        #pragma unroll
        for (int nt = 0; nt < 8; nt++) {
            int col = nt * 8 + tig * 2;
            float vx = vs[col], vy = vs[col + 1];
            float2 o0 = make_float2((acc[mt][nt][0] + vx) * inv0, (acc[mt][nt][1] + vy) * inv0);
            float2 o1 = make_float2((acc[mt][nt][2] + vx) * inv1, (acc[mt][nt][3] + vy) * inv1);
            *(float2*)&out[g0 + col] = o0;
            *(float2*)&out[g1 + col] = o1;
        }
    }
}

// ---------------- launch ------------------------------------------------------
extern "C" void kernel_launch(void* const* d_in, const int* in_sizes, int n_in,
                              void* d_out, int out_size)
{
    const float* X  = (const float*)d_in[0];
    const float* am = (const float*)d_in[1];
    const float* Wq = (const float*)d_in[2];
    const float* bq = (const float*)d_in[3];
    const float* Wk = (const float*)d_in[4];
    const float* bk = (const float*)d_in[5];
    const float* Wv = (const float*)d_in[6];
    const float* bv = (const float*)d_in[7];
    float* out = (float*)d_out;

    cudaFuncSetAttribute(out_mma, cudaFuncAttributeMaxDynamicSharedMemorySize, OUT_SMEM);

    zero_kernel<<<(RED_TOTAL + 255) / 256, 256>>>();
    msum_kernel<<<Bb, 256>>>(am);

    dim3 g1(18, 256);
    gemm_qkv_mma<<<g1, 256>>>(X, am, Wq, bq, Wk, bk, Wv, bv);

    dim3 g3(48, 8);
    kv_kernel<<<g3, 256>>>();

    dim3 g4(48, 64);
    out_mma<<<g4, 128, OUT_SMEM>>>(out);
}

// round 5
// speedup vs baseline: 5.6033x; 1.9039x over previous
#include <cuda_runtime.h>
#include <cuda_fp16.h>
#include <cstdint>

// Problem constants
#define Bb   4
#define Ss   8192
#define HID  768
#define NH   12
#define HD   64
#define ROWS (Bb*Ss)          // 32768
#define EPS  1e-5f

// ---------------- scratch (device globals; no allocations allowed) ----------
__device__ float g_Q[(size_t)ROWS * HID];
__device__ float g_K[(size_t)ROWS * HID];
__device__ float g_V[(size_t)ROWS * HID];
__device__ __half g_Xh[(size_t)ROWS * HID];          // fp16 copy of X
__device__ __half g_Wh[(size_t)3 * HID * HID];       // fp16 [Wq;Wk;Wv]

#define KV_OFF   0                       // 48 * 64 * 64
#define KSUM_OFF (48*4096)               // 48 * 64
#define VSUM_OFF (KSUM_OFF + 48*64)
#define MSUM_OFF (VSUM_OFF + 48*64)
#define RED_TOTAL (MSUM_OFF + 4)
__device__ float g_red[RED_TOTAL];

// ---------------- K0: zero the reduction scratch ----------------------------
__global__ void zero_kernel() {
    int i = blockIdx.x * 256 + threadIdx.x;
    if (i < RED_TOTAL) g_red[i] = 0.0f;
}

// ================= helpers ====================================================
__device__ __forceinline__ uint32_t smem_u32(const void* p) {
    uint32_t a;
    asm("{ .reg .u64 t; cvta.to.shared.u64 t, %1; cvt.u32.u64 %0, t; }" : "=r"(a) : "l"(p));
    return a;
}
#define CP_ASYNC16(dst, src) \
    asm volatile("cp.async.cg.shared.global [%0], [%1], 16;" :: "r"((uint32_t)(dst)), "l"(src) : "memory")
#define CP_COMMIT() asm volatile("cp.async.commit_group;" ::: "memory")
#define SWZ(o) ((o) ^ (((o) >> 3) & 0x70))

__device__ __forceinline__ uint32_t f2tf32(float f) {
    uint32_t r;
    asm("cvt.rna.tf32.f32 %0, %1;" : "=r"(r) : "f"(f));
    return r;
}
__device__ __forceinline__ void mma_tf32(float* d, const uint32_t* a, const uint32_t* b) {
    asm volatile(
        "mma.sync.aligned.m16n8k8.row.col.f32.tf32.tf32.f32 "
        "{%0,%1,%2,%3}, {%4,%5,%6,%7}, {%8,%9}, {%0,%1,%2,%3};"
        : "+f"(d[0]), "+f"(d[1]), "+f"(d[2]), "+f"(d[3])
        : "r"(a[0]), "r"(a[1]), "r"(a[2]), "r"(a[3]), "r"(b[0]), "r"(b[1]));
}
__device__ __forceinline__ void mma_f16(float* d, const uint32_t* a, const uint32_t* b) {
    asm volatile(
        "mma.sync.aligned.m16n8k16.row.col.f32.f16.f16.f32 "
        "{%0,%1,%2,%3}, {%4,%5,%6,%7}, {%8,%9}, {%0,%1,%2,%3};"
        : "+f"(d[0]), "+f"(d[1]), "+f"(d[2]), "+f"(d[3])
        : "r"(a[0]), "r"(a[1]), "r"(a[2]), "r"(a[3]), "r"(b[0]), "r"(b[1]));
}
#define LDMATRIX_X4(r, addr) \
    asm volatile("ldmatrix.sync.aligned.m8n8.x4.shared.b16 {%0,%1,%2,%3}, [%4];" \
        : "=r"((r)[0]), "=r"((r)[1]), "=r"((r)[2]), "=r"((r)[3]) : "r"(addr))

// ---------------- K-1: fp32 -> fp16 converters --------------------------------
__global__ void convX_kernel(const float* __restrict__ X) {
    size_t i = (size_t)blockIdx.x * 256 + threadIdx.x;   // float4 index
    float4 v = ((const float4*)X)[i];
    __half2 h0 = __floats2half2_rn(v.x, v.y);
    __half2 h1 = __floats2half2_rn(v.z, v.w);
    ((__half2*)g_Xh)[2*i]   = h0;
    ((__half2*)g_Xh)[2*i+1] = h1;
}
__global__ void convW_kernel(const float* __restrict__ Wq,
                             const float* __restrict__ Wk,
                             const float* __restrict__ Wv) {
    size_t i = (size_t)blockIdx.x * 256 + threadIdx.x;   // float4 index, 0..442367
    const size_t per = (size_t)HID * HID / 4;            // 147456
    const float* src = (i < per) ? Wq : (i < 2*per) ? Wk : Wv;
    size_t j = i % per;
    float4 v = ((const float4*)src)[j];
    __half2 h0 = __floats2half2_rn(v.x, v.y);
    __half2 h1 = __floats2half2_rn(v.z, v.w);
    ((__half2*)g_Wh)[2*i]   = h0;
    ((__half2*)g_Wh)[2*i+1] = h1;
}

// ---------------- K1: fused QKV projection (fp16 HMMA) + mask + L2-norm -------
// C = X[32768,768] @ W^T. 128x128x64 CTA tile, 8 warps (2m x 4n), warp 64x32.
// fp16 operands in SW128 smem, ldmatrix fragments, m16n8k16 MMA, fp32 accum.
// Grid (18, 256). Epilogue: Q,K mask + per-(row,head) L2 normalize.
#define GK_SMEM (65536 + 1024)   // A 2x16KB, B 2x16KB, ssqs 1KB

__global__ void __launch_bounds__(256, 2) gemm_qkv_h(
    const float* __restrict__ am,
    const float* __restrict__ bq, const float* __restrict__ bk, const float* __restrict__ bv)
{
    extern __shared__ char smem[];
    const uint32_t sb = smem_u32(smem);
    float* ssqs = (float*)(smem + 65536);   // [128][2]

    const int t    = threadIdx.x;
    const int wid  = t >> 5, lane = t & 31;
    const int wm   = wid & 1,  wn  = wid >> 2;        // note: wn in 0..? fix below
    // 8 warps: wm = wid & 1 (2 in m), wn2 = wid >> 1 (4 in n)
    const int wnn  = wid >> 1;
    const int grp  = lane >> 2, tig = lane & 3;

    const int nb = blockIdx.x;          // 0..17
    const int mb = blockIdx.y;          // 0..255
    const int mat = nb / 6;             // 0=q 1=k 2=v
    const float* bias = (mat == 0) ? bq : (mat == 1) ? bk : bv;
    float* C          = (mat == 0) ? g_Q : (mat == 1) ? g_K : g_V;
    const int n0 = (nb % 6) * 128;      // column offset within the 768 output
    const int m0 = mb * 128;

    const __half* Asrc = g_Xh + (size_t)m0 * 768;
    const __half* Bsrc = g_Wh + (size_t)nb * 128 * 768;

    auto load_tile = [&](int kt, int buf) {
        uint32_t Ad = sb + buf * 16384;
        uint32_t Bd = sb + 32768 + buf * 16384;
        #pragma unroll
        for (int i = 0; i < 4; i++) {
            int s   = t + i * 256;          // 0..1023
            int row = s >> 3, ch = s & 7;   // 16B chunk within 128B row
            uint32_t off = (uint32_t)(row * 128 + ch * 16);
            const __half* as = Asrc + (size_t)row * 768 + kt * 64 + ch * 8;
            const __half* bs = Bsrc + (size_t)row * 768 + kt * 64 + ch * 8;
            CP_ASYNC16(Ad + SWZ(off), as);
            CP_ASYNC16(Bd + SWZ(off), bs);
        }
        CP_COMMIT();
    };

    float acc[4][4][4];
    #pragma unroll
    for (int i = 0; i < 4; i++)
        #pragma unroll
        for (int j = 0; j < 4; j++)
            #pragma unroll
            for (int c = 0; c < 4; c++) acc[i][j][c] = 0.0f;

    load_tile(0, 0);

    for (int kt = 0; kt < 12; kt++) {
        const int buf = kt & 1;
        if (kt + 1 < 12) {
            load_tile(kt + 1, buf ^ 1);
            asm volatile("cp.async.wait_group 1;" ::: "memory");
        } else {
            asm volatile("cp.async.wait_group 0;" ::: "memory");
        }
        __syncthreads();

        const uint32_t Abase = sb + buf * 16384;
        const uint32_t Bbase = sb + 32768 + buf * 16384;

        #pragma unroll
        for (int ks = 0; ks < 4; ks++) {
            const int k0b = ks * 32;   // byte offset of k0 within 128B row
            uint32_t afr[4][4];
            #pragma unroll
            for (int mt = 0; mt < 4; mt++) {
                int row = wm * 64 + mt * 16 + (lane & 15);
                uint32_t off = (uint32_t)(row * 128 + k0b + (lane >> 4) * 16);
                LDMATRIX_X4(afr[mt], Abase + SWZ(off));
            }
            uint32_t bfr[2][4];
            #pragma unroll
            for (int bp = 0; bp < 2; bp++) {
                int row = wnn * 32 + bp * 16 + (lane & 7) + ((lane >> 4) << 3);
                uint32_t off = (uint32_t)(row * 128 + k0b + ((lane >> 3) & 1) * 16);
                LDMATRIX_X4(bfr[bp], Bbase + SWZ(off));
            }
            #pragma unroll
            for (int mt = 0; mt < 4; mt++)
                #pragma unroll
                for (int nt = 0; nt < 4; nt++)
                    mma_f16(acc[mt][nt], afr[mt], &bfr[nt >> 1][(nt & 1) * 2]);
        }
        __syncthreads();
    }

    // -------- epilogue --------
    const int rbase = m0 + wm * 64;
    const int cbase = n0 + wnn * 32;
    const int head  = wnn >> 1;          // which of the 2 heads in this n-tile

    if (mat < 2) {
        ssqs[t >> 1 << 1 | (t & 1)] = 0.0f;   // ssqs[128][2] zero
        __syncthreads();

        float mrow[4][2];
        #pragma unroll
        for (int mt = 0; mt < 4; mt++) {
            mrow[mt][0] = (am[m0 + wm*64 + mt*16 + grp]     != 0.0f) ? 0.0f : 1.0f;
            mrow[mt][1] = (am[m0 + wm*64 + mt*16 + grp + 8] != 0.0f) ? 0.0f : 1.0f;
        }
        float part[4][2];
        #pragma unroll
        for (int mt = 0; mt < 4; mt++) { part[mt][0] = 0.0f; part[mt][1] = 0.0f; }

        #pragma unroll
        for (int nt = 0; nt < 4; nt++) {
            int col = cbase + nt * 8 + tig * 2;
            float bx = bias[col], by = bias[col + 1];
            #pragma unroll
            for (int mt = 0; mt < 4; mt++) {
                float a0 = (acc[mt][nt][0] + bx) * mrow[mt][0];
                float a1 = (acc[mt][nt][1] + by) * mrow[mt][0];
                float a2 = (acc[mt][nt][2] + bx) * mrow[mt][1];
                float a3 = (acc[mt][nt][3] + by) * mrow[mt][1];
                acc[mt][nt][0] = a0; acc[mt][nt][1] = a1;
                acc[mt][nt][2] = a2; acc[mt][nt][3] = a3;
                part[mt][0] += a0*a0 + a1*a1;
                part[mt][1] += a2*a2 + a3*a3;
            }
        }
        #pragma unroll
        for (int off = 1; off <= 2; off <<= 1)
            #pragma unroll
            for (int mt = 0; mt < 4; mt++) {
                part[mt][0] += __shfl_xor_sync(0xffffffffu, part[mt][0], off);
                part[mt][1] += __shfl_xor_sync(0xffffffffu, part[mt][1], off);
            }
        if (tig == 0) {
            #pragma unroll
            for (int mt = 0; mt < 4; mt++) {
                atomicAdd(&ssqs[(wm*64 + mt*16 + grp) * 2 + head],     part[mt][0]);
                atomicAdd(&ssqs[(wm*64 + mt*16 + grp + 8) * 2 + head], part[mt][1]);
            }
        }
        __syncthreads();

        float inv[4][2];
        #pragma unroll
        for (int mt = 0; mt < 4; mt++) {
            inv[mt][0] = 1.0f / (sqrtf(ssqs[(wm*64 + mt*16 + grp) * 2 + head])     + EPS);
            inv[mt][1] = 1.0f / (sqrtf(ssqs[(wm*64 + mt*16 + grp + 8) * 2 + head]) + EPS);
        }
        #pragma unroll
        for (int nt = 0; nt < 4; nt++) {
            int col = cbase + nt * 8 + tig * 2;
            #pragma unroll
            for (int mt = 0; mt < 4; mt++) {
                size_t r0 = (size_t)(rbase + mt * 16 + grp) * 768 + col;
                float2 v0 = make_float2(acc[mt][nt][0] * inv[mt][0], acc[mt][nt][1] * inv[mt][0]);
                float2 v1 = make_float2(acc[mt][nt][2] * inv[mt][1], acc[mt][nt][3] * inv[mt][1]);
                *(float2*)&C[r0]           = v0;
                *(float2*)&C[r0 + 8 * 768] = v1;
            }
        }
    } else {
        #pragma unroll
        for (int nt = 0; nt < 4; nt++) {
            int col = cbase + nt * 8 + tig * 2;
            float bx = bias[col], by = bias[col + 1];
            #pragma unroll
            for (int mt = 0; mt < 4; mt++) {
                size_t r0 = (size_t)(rbase + mt * 16 + grp) * 768 + col;
                float2 v0 = make_float2(acc[mt][nt][0] + bx, acc[mt][nt][1] + by);
                float2 v1 = make_float2(acc[mt][nt][2] + bx, acc[mt][nt][3] + by);
                *(float2*)&C[r0]           = v0;
                *(float2*)&C[r0 + 8 * 768] = v1;
            }
        }
    }
}

// ---------------- K2b: msum per batch ----------------------------------------
__global__ void msum_kernel(const float* __restrict__ am) {
    __shared__ float red[256];
    int b = blockIdx.x;
    float s = 0.0f;
    for (int i = threadIdx.x; i < Ss; i += 256)
        s += (am[b * Ss + i] != 0.0f) ? 0.0f : 1.0f;
    red[threadIdx.x] = s;
    __syncthreads();
    for (int o = 128; o; o >>= 1) {
        if (threadIdx.x < o) red[threadIdx.x] += red[threadIdx.x + o];
        __syncthreads();
    }
    if (threadIdx.x == 0) g_red[MSUM_OFF + b] = red[0];
}

// ---------------- K3: kv = K^T V, ksum, vsum per (b,h) ----------------------
// grid (48, 32): each block handles 256 s-positions, atomically accumulated
__global__ __launch_bounds__(256) void kv_kernel() {
    int bh = blockIdx.x;
    int b = bh / NH, h = bh % NH;
    int sc = blockIdx.y;

    __shared__ float ks[32][64];
    __shared__ float vs[32][64];

    int t  = threadIdx.x;
    int tx = t & 15, ty = t >> 4;
    float acc[4][4];
    #pragma unroll
    for (int i = 0; i < 4; i++)
        #pragma unroll
        for (int j = 0; j < 4; j++) acc[i][j] = 0.0f;
    float ksum = 0.0f, vsum = 0.0f;

    for (int s0 = sc * 256; s0 < sc * 256 + 256; s0 += 32) {
        __syncthreads();
        #pragma unroll
        for (int p = 0; p < 2; p++) {
            int f = t + p * 256;
            int row = f >> 4, c4 = (f & 15) * 4;
            size_t gi = ((size_t)(b * Ss + s0 + row)) * HID + h * HD + c4;
            *(float4*)&ks[row][c4] = *(const float4*)&g_K[gi];
            *(float4*)&vs[row][c4] = *(const float4*)&g_V[gi];
        }
        __syncthreads();
        #pragma unroll 8
        for (int ss = 0; ss < 32; ss++) {
            float4 ka = *(float4*)&ks[ss][tx*4];
            float4 va = *(float4*)&vs[ss][ty*4];
            float kk[4] = {ka.x, ka.y, ka.z, ka.w};
            float vv[4] = {va.x, va.y, va.z, va.w};
            #pragma unroll
            for (int i = 0; i < 4; i++)
                #pragma unroll
                for (int j = 0; j < 4; j++)
                    acc[i][j] = fmaf(kk[i], vv[j], acc[i][j]);
        }
        if (t < 64)       { for (int ss = 0; ss < 32; ss++) ksum += ks[ss][t]; }
        else if (t < 128) { for (int ss = 0; ss < 32; ss++) vsum += vs[ss][t - 64]; }
    }

    float* kvb = g_red + KV_OFF + bh * 4096;
    #pragma unroll
    for (int i = 0; i < 4; i++)
        #pragma unroll
        for (int j = 0; j < 4; j++)
            atomicAdd(&kvb[(tx*4 + i) * 64 + ty*4 + j], acc[i][j]);
    if (t < 64)       atomicAdd(&g_red[KSUM_OFF + bh * 64 + t], ksum);
    else if (t < 128) atomicAdd(&g_red[VSUM_OFF + bh * 64 + (t - 64)], vsum);
}

// ---------------- K4: out via tensor cores (tf32) ----------------------------
#define QP 68   // Q smem row pitch (floats)
#define OUT_SMEM ((128*QP + 72*QP + 128 + 64) * 4)

__global__ void __launch_bounds__(128) out_mma(float* __restrict__ out) {
    extern __shared__ float sm[];
    float* Qs  = sm;                 // [128][QP]
    float* kvT = sm + 128 * QP;      // [72][QP]
    float* nqs = kvT + 72 * QP;      // [128]
    float* vs  = nqs + 128;          // [64]

    const int bh = blockIdx.x, st = blockIdx.y;
    const int b = bh / NH, h = bh % NH;
    const int t = threadIdx.x;
    const int wid = t >> 5, lane = t & 31;
    const int grp = lane >> 2, tig = lane & 3;

    const uint32_t sQ = smem_u32(Qs);
    #pragma unroll
    for (int i = 0; i < 16; i++) {
        int s = t + i * 128;         // 0..2047
        int row = s >> 4, c = s & 15;
        CP_ASYNC16(sQ + (uint32_t)(row * QP + c * 4) * 4u,
                   g_Q + ((size_t)(b * Ss + st * 128 + row)) * HID + h * HD + c * 4);
    }
    CP_COMMIT();

    for (int idx = t; idx < 72 * 64; idx += 128) {
        int n = idx >> 6, k = idx & 63;
        float v;
        if (n < 64)       v = g_red[KV_OFF + bh * 4096 + k * 64 + n];
        else if (n == 64) v = g_red[KSUM_OFF + bh * 64 + k];
        else              v = 0.0f;
        kvT[n * QP + k] = v;
    }
    if (t < 64) vs[t] = g_red[VSUM_OFF + bh * 64 + t];
    const float msum = g_red[MSUM_OFF + b];

    asm volatile("cp.async.wait_group 0;" ::: "memory");
    __syncthreads();

    float acc[2][9][4];
    #pragma unroll
    for (int i = 0; i < 2; i++)
        #pragma unroll
        for (int j = 0; j < 9; j++)
            #pragma unroll
            for (int c = 0; c < 4; c++) acc[i][j][c] = 0.0f;

    #pragma unroll
    for (int ks = 0; ks < 8; ks++) {
        const int k0 = ks * 8;
        uint32_t afr[2][4];
        #pragma unroll
        for (int mt = 0; mt < 2; mt++) {
            int m = wid * 32 + mt * 16;
            afr[mt][0] = f2tf32(Qs[(m + grp)     * QP + k0 + tig]);
            afr[mt][1] = f2tf32(Qs[(m + grp + 8) * QP + k0 + tig]);
            afr[mt][2] = f2tf32(Qs[(m + grp)     * QP + k0 + tig + 4]);
            afr[mt][3] = f2tf32(Qs[(m + grp + 8) * QP + k0 + tig + 4]);
        }
        #pragma unroll
        for (int nt = 0; nt < 9; nt++) {
            uint32_t bfr[2];
            bfr[0] = f2tf32(kvT[(nt * 8 + grp) * QP + k0 + tig]);
            bfr[1] = f2tf32(kvT[(nt * 8 + grp) * QP + k0 + tig + 4]);
            #pragma unroll
            for (int mt = 0; mt < 2; mt++)
                mma_tf32(acc[mt][nt], afr[mt], bfr);
        }
    }

    if (tig == 0) {
        #pragma unroll
        for (int mt = 0; mt < 2; mt++) {
            nqs[wid * 32 + mt * 16 + grp]     = acc[mt][8][0];
            nqs[wid * 32 + mt * 16 + grp + 8] = acc[mt][8][2];
        }
    }
    __syncthreads();

    #pragma unroll
    for (int mt = 0; mt < 2; mt++) {
        int r0 = wid * 32 + mt * 16 + grp;
        float inv0 = 1.0f / (nqs[r0]     + EPS + msum);
        float inv1 = 1.0f / (nqs[r0 + 8] + EPS + msum);
        size_t g0 = ((size_t)(b * Ss + st * 128 + r0))     * HID + h * HD;
        size_t g1 = ((size_t)(b * Ss + st * 128 + r0 + 8)) * HID + h * HD;
        #pragma unroll
        for (int nt = 0; nt < 8; nt++) {
            int col = nt * 8 + tig * 2;
            float vx = vs[col], vy = vs[col + 1];
            float2 o0 = make_float2((acc[mt][nt][0] + vx) * inv0, (acc[mt][nt][1] + vy) * inv0);
            float2 o1 = make_float2((acc[mt][nt][2] + vx) * inv1, (acc[mt][nt][3] + vy) * inv1);
            *(float2*)&out[g0 + col] = o0;
            *(float2*)&out[g1 + col] = o1;
        }
    }
}

// ---------------- launch ------------------------------------------------------
extern "C" void kernel_launch(void* const* d_in, const int* in_sizes, int n_in,
                              void* d_out, int out_size)
{
    const float* X  = (const float*)d_in[0];
    const float* am = (const float*)d_in[1];
    const float* Wq = (const float*)d_in[2];
    const float* bq = (const float*)d_in[3];
    const float* Wk = (const float*)d_in[4];
    const float* bk = (const float*)d_in[5];
    const float* Wv = (const float*)d_in[6];
    const float* bv = (const float*)d_in[7];
    float* out = (float*)d_out;

    cudaFuncSetAttribute(gemm_qkv_h, cudaFuncAttributeMaxDynamicSharedMemorySize, GK_SMEM);
    cudaFuncSetAttribute(out_mma, cudaFuncAttributeMaxDynamicSharedMemorySize, OUT_SMEM);

    zero_kernel<<<(RED_TOTAL + 255) / 256, 256>>>();
    msum_kernel<<<Bb, 256>>>(am);

    convX_kernel<<<(ROWS * HID / 4) / 256, 256>>>(X);
    convW_kernel<<<(3 * HID * HID / 4) / 256, 256>>>(Wq, Wk, Wv);

    dim3 g1(18, 256);
    gemm_qkv_h<<<g1, 256, GK_SMEM>>>(am, bq, bk, bv);

    dim3 g3(48, 32);
    kv_kernel<<<g3, 256>>>();

    dim3 g4(48, 64);
    out_mma<<<g4, 128, OUT_SMEM>>>(out);
}

// round 6
// speedup vs baseline: 6.9298x; 1.2367x over previous
#include <cuda_runtime.h>
#include <cuda_fp16.h>
#include <cstdint>

// Problem constants
#define Bb   4
#define Ss   8192
#define HID  768
#define NH   12
#define HD   64
#define ROWS (Bb*Ss)          // 32768
#define EPS  1e-5f

// ---------------- scratch (device globals; no allocations allowed) ----------
__device__ __half g_Qh[(size_t)ROWS * HID];
__device__ __half g_Kh[(size_t)ROWS * HID];
__device__ __half g_Vh[(size_t)ROWS * HID];
__device__ __half g_Xh[(size_t)ROWS * HID];          // fp16 copy of X
__device__ __half g_Wh[(size_t)3 * HID * HID];       // fp16 [Wq;Wk;Wv]

#define KV_OFF   0                       // 48 * 64 * 64
#define KSUM_OFF (48*4096)               // 48 * 64
#define VSUM_OFF (KSUM_OFF + 48*64)
#define MSUM_OFF (VSUM_OFF + 48*64)
#define RED_TOTAL (MSUM_OFF + 4)
__device__ float g_red[RED_TOTAL];

// ---------------- K0: zero the reduction scratch ----------------------------
__global__ void zero_kernel() {
    int i = blockIdx.x * 256 + threadIdx.x;
    if (i < RED_TOTAL) g_red[i] = 0.0f;
}

// ================= helpers ====================================================
__device__ __forceinline__ uint32_t smem_u32(const void* p) {
    uint32_t a;
    asm("{ .reg .u64 t; cvta.to.shared.u64 t, %1; cvt.u32.u64 %0, t; }" : "=r"(a) : "l"(p));
    return a;
}
#define CP_ASYNC16(dst, src) \
    asm volatile("cp.async.cg.shared.global [%0], [%1], 16;" :: "r"((uint32_t)(dst)), "l"(src) : "memory")
#define CP_COMMIT() asm volatile("cp.async.commit_group;" ::: "memory")
#define SWZ(o) ((o) ^ (((o) >> 3) & 0x70))

__device__ __forceinline__ void mma_f16(float* d, const uint32_t* a, const uint32_t* b) {
    asm volatile(
        "mma.sync.aligned.m16n8k16.row.col.f32.f16.f16.f32 "
        "{%0,%1,%2,%3}, {%4,%5,%6,%7}, {%8,%9}, {%0,%1,%2,%3};"
        : "+f"(d[0]), "+f"(d[1]), "+f"(d[2]), "+f"(d[3])
        : "r"(a[0]), "r"(a[1]), "r"(a[2]), "r"(a[3]), "r"(b[0]), "r"(b[1]));
}
#define LDMATRIX_X4(r, addr) \
    asm volatile("ldmatrix.sync.aligned.m8n8.x4.shared.b16 {%0,%1,%2,%3}, [%4];" \
        : "=r"((r)[0]), "=r"((r)[1]), "=r"((r)[2]), "=r"((r)[3]) : "r"(addr))
#define LDMATRIX_X4_T(r, addr) \
    asm volatile("ldmatrix.sync.aligned.m8n8.x4.trans.shared.b16 {%0,%1,%2,%3}, [%4];" \
        : "=r"((r)[0]), "=r"((r)[1]), "=r"((r)[2]), "=r"((r)[3]) : "r"(addr))
#define ONES2 0x3C003C00u   // half2(1.0, 1.0)

// ---------------- K-1: fp32 -> fp16 converters --------------------------------
__global__ void convX_kernel(const float* __restrict__ X) {
    size_t i = (size_t)blockIdx.x * 256 + threadIdx.x;   // float4 index
    float4 v = ((const float4*)X)[i];
    ((__half2*)g_Xh)[2*i]   = __floats2half2_rn(v.x, v.y);
    ((__half2*)g_Xh)[2*i+1] = __floats2half2_rn(v.z, v.w);
}
__global__ void convW_kernel(const float* __restrict__ Wq,
                             const float* __restrict__ Wk,
                             const float* __restrict__ Wv) {
    size_t i = (size_t)blockIdx.x * 256 + threadIdx.x;   // float4 index
    const size_t per = (size_t)HID * HID / 4;            // 147456
    const float* src = (i < per) ? Wq : (i < 2*per) ? Wk : Wv;
    size_t j = i % per;
    float4 v = ((const float4*)src)[j];
    ((__half2*)g_Wh)[2*i]   = __floats2half2_rn(v.x, v.y);
    ((__half2*)g_Wh)[2*i+1] = __floats2half2_rn(v.z, v.w);
}

// ---------------- K1: fused QKV projection (fp16 HMMA) + mask + L2-norm -------
// C = X[32768,768] @ W^T. 128x128x64 CTA tile, 8 warps (2m x 4n), warp 64x32.
// Epilogue: Q,K mask + per-(row,head) L2 normalize; store fp16.
#define GK_SMEM (65536 + 1024)

__global__ void __launch_bounds__(256, 2) gemm_qkv_h(
    const float* __restrict__ am,
    const float* __restrict__ bq, const float* __restrict__ bk, const float* __restrict__ bv)
{
    extern __shared__ char smem[];
    const uint32_t sb = smem_u32(smem);
    float* ssqs = (float*)(smem + 65536);   // [128][2]

    const int t    = threadIdx.x;
    const int wid  = t >> 5, lane = t & 31;
    const int wm   = wid & 1;
    const int wnn  = wid >> 1;
    const int grp  = lane >> 2, tig = lane & 3;

    const int nb = blockIdx.x;          // 0..17
    const int mb = blockIdx.y;          // 0..255
    const int mat = nb / 6;             // 0=q 1=k 2=v
    const float* bias = (mat == 0) ? bq : (mat == 1) ? bk : bv;
    __half* C         = (mat == 0) ? g_Qh : (mat == 1) ? g_Kh : g_Vh;
    const int n0 = (nb % 6) * 128;
    const int m0 = mb * 128;

    const __half* Asrc = g_Xh + (size_t)m0 * 768;
    const __half* Bsrc = g_Wh + (size_t)nb * 128 * 768;

    auto load_tile = [&](int kt, int buf) {
        uint32_t Ad = sb + buf * 16384;
        uint32_t Bd = sb + 32768 + buf * 16384;
        #pragma unroll
        for (int i = 0; i < 4; i++) {
            int s   = t + i * 256;
            int row = s >> 3, ch = s & 7;
            uint32_t off = (uint32_t)(row * 128 + ch * 16);
            CP_ASYNC16(Ad + SWZ(off), Asrc + (size_t)row * 768 + kt * 64 + ch * 8);
            CP_ASYNC16(Bd + SWZ(off), Bsrc + (size_t)row * 768 + kt * 64 + ch * 8);
        }
        CP_COMMIT();
    };

    float acc[4][4][4];
    #pragma unroll
    for (int i = 0; i < 4; i++)
        #pragma unroll
        for (int j = 0; j < 4; j++)
            #pragma unroll
            for (int c = 0; c < 4; c++) acc[i][j][c] = 0.0f;

    load_tile(0, 0);

    for (int kt = 0; kt < 12; kt++) {
        const int buf = kt & 1;
        if (kt + 1 < 12) {
            load_tile(kt + 1, buf ^ 1);
            asm volatile("cp.async.wait_group 1;" ::: "memory");
        } else {
            asm volatile("cp.async.wait_group 0;" ::: "memory");
        }
        __syncthreads();

        const uint32_t Abase = sb + buf * 16384;
        const uint32_t Bbase = sb + 32768 + buf * 16384;

        #pragma unroll
        for (int ks = 0; ks < 4; ks++) {
            const int k0b = ks * 32;
            uint32_t afr[4][4];
            #pragma unroll
            for (int mt = 0; mt < 4; mt++) {
                int row = wm * 64 + mt * 16 + (lane & 15);
                uint32_t off = (uint32_t)(row * 128 + k0b + (lane >> 4) * 16);
                LDMATRIX_X4(afr[mt], Abase + SWZ(off));
            }
            uint32_t bfr[2][4];
            #pragma unroll
            for (int bp = 0; bp < 2; bp++) {
                int row = wnn * 32 + bp * 16 + (lane & 7) + ((lane >> 4) << 3);
                uint32_t off = (uint32_t)(row * 128 + k0b + ((lane >> 3) & 1) * 16);
                LDMATRIX_X4(bfr[bp], Bbase + SWZ(off));
            }
            #pragma unroll
            for (int mt = 0; mt < 4; mt++)
                #pragma unroll
                for (int nt = 0; nt < 4; nt++)
                    mma_f16(acc[mt][nt], afr[mt], &bfr[nt >> 1][(nt & 1) * 2]);
        }
        __syncthreads();
    }

    // -------- epilogue --------
    const int rbase = m0 + wm * 64;
    const int cbase = n0 + wnn * 32;
    const int head  = wnn >> 1;

    if (mat < 2) {
        ssqs[t] = 0.0f; if (t < 256) {}           // zero [128][2] = 256 floats
        __syncthreads();

        float mrow[4][2];
        #pragma unroll
        for (int mt = 0; mt < 4; mt++) {
            mrow[mt][0] = (am[m0 + wm*64 + mt*16 + grp]     != 0.0f) ? 0.0f : 1.0f;
            mrow[mt][1] = (am[m0 + wm*64 + mt*16 + grp + 8] != 0.0f) ? 0.0f : 1.0f;
        }
        float part[4][2];
        #pragma unroll
        for (int mt = 0; mt < 4; mt++) { part[mt][0] = 0.0f; part[mt][1] = 0.0f; }

        #pragma unroll
        for (int nt = 0; nt < 4; nt++) {
            int col = cbase + nt * 8 + tig * 2;
            float bx = bias[col], by = bias[col + 1];
            #pragma unroll
            for (int mt = 0; mt < 4; mt++) {
                float a0 = (acc[mt][nt][0] + bx) * mrow[mt][0];
                float a1 = (acc[mt][nt][1] + by) * mrow[mt][0];
                float a2 = (acc[mt][nt][2] + bx) * mrow[mt][1];
                float a3 = (acc[mt][nt][3] + by) * mrow[mt][1];
                acc[mt][nt][0] = a0; acc[mt][nt][1] = a1;
                acc[mt][nt][2] = a2; acc[mt][nt][3] = a3;
                part[mt][0] += a0*a0 + a1*a1;
                part[mt][1] += a2*a2 + a3*a3;
            }
        }
        #pragma unroll
        for (int off = 1; off <= 2; off <<= 1)
            #pragma unroll
            for (int mt = 0; mt < 4; mt++) {
                part[mt][0] += __shfl_xor_sync(0xffffffffu, part[mt][0], off);
                part[mt][1] += __shfl_xor_sync(0xffffffffu, part[mt][1], off);
            }
        if (tig == 0) {
            #pragma unroll
            for (int mt = 0; mt < 4; mt++) {
                atomicAdd(&ssqs[(wm*64 + mt*16 + grp) * 2 + head],     part[mt][0]);
                atomicAdd(&ssqs[(wm*64 + mt*16 + grp + 8) * 2 + head], part[mt][1]);
            }
        }
        __syncthreads();

        float inv[4][2];
        #pragma unroll
        for (int mt = 0; mt < 4; mt++) {
            inv[mt][0] = 1.0f / (sqrtf(ssqs[(wm*64 + mt*16 + grp) * 2 + head])     + EPS);
            inv[mt][1] = 1.0f / (sqrtf(ssqs[(wm*64 + mt*16 + grp + 8) * 2 + head]) + EPS);
        }
        #pragma unroll
        for (int nt = 0; nt < 4; nt++) {
            int col = cbase + nt * 8 + tig * 2;
            #pragma unroll
            for (int mt = 0; mt < 4; mt++) {
                size_t r0 = (size_t)(rbase + mt * 16 + grp) * 768 + col;
                *(__half2*)&C[r0]           = __floats2half2_rn(acc[mt][nt][0] * inv[mt][0], acc[mt][nt][1] * inv[mt][0]);
                *(__half2*)&C[r0 + 8 * 768] = __floats2half2_rn(acc[mt][nt][2] * inv[mt][1], acc[mt][nt][3] * inv[mt][1]);
            }
        }
    } else {
        #pragma unroll
        for (int nt = 0; nt < 4; nt++) {
            int col = cbase + nt * 8 + tig * 2;
            float bx = bias[col], by = bias[col + 1];
            #pragma unroll
            for (int mt = 0; mt < 4; mt++) {
                size_t r0 = (size_t)(rbase + mt * 16 + grp) * 768 + col;
                *(__half2*)&C[r0]           = __floats2half2_rn(acc[mt][nt][0] + bx, acc[mt][nt][1] + by);
                *(__half2*)&C[r0 + 8 * 768] = __floats2half2_rn(acc[mt][nt][2] + bx, acc[mt][nt][3] + by);
            }
        }
    }
}

// ---------------- K2b: msum per batch ----------------------------------------
__global__ void msum_kernel(const float* __restrict__ am) {
    __shared__ float red[256];
    int b = blockIdx.x;
    float s = 0.0f;
    for (int i = threadIdx.x; i < Ss; i += 256)
        s += (am[b * Ss + i] != 0.0f) ? 0.0f : 1.0f;
    red[threadIdx.x] = s;
    __syncthreads();
    for (int o = 128; o; o >>= 1) {
        if (threadIdx.x < o) red[threadIdx.x] += red[threadIdx.x + o];
        __syncthreads();
    }
    if (threadIdx.x == 0) g_red[MSUM_OFF + b] = red[0];
}

// ---------------- K3: kv = K^T V (+ ksum, vsum) via HMMA ----------------------
// Per (bh, sc): A = K^T (trans-ldmatrix), B = V^T (trans-ldmatrix), fp32 acc.
// 5 warps: w<4 -> kv rows 16w..16w+15 (+ ksum via constant ones-col B n-tile 8);
//          w=4 -> constant ones-row A fragment -> vsum.
// Grid (48, 16): each CTA reduces 512 s-positions; atomicAdd to g_red.
__global__ void __launch_bounds__(160) kv_mma() {
    __shared__ __half Ks[2][64 * 64];
    __shared__ __half Vs[2][64 * 64];

    const int bh = blockIdx.x, sc = blockIdx.y;
    const int b = bh / NH, h = bh % NH;
    const int t = threadIdx.x;
    const int wid = t >> 5, lane = t & 31;
    const int grp = lane >> 2, tig = lane & 3;
    const uint32_t sK = smem_u32(Ks);
    const uint32_t sV = smem_u32(Vs);
    const int s_base = sc * 512;

    auto load_tile = [&](int tile, int buf) {
        int s0 = s_base + tile * 64;
        for (int i = t; i < 1024; i += 160) {
            int isV = i >> 9;                  // 0: K, 1: V
            int j = i & 511;
            int row = j >> 3, ch = j & 7;
            uint32_t off = SWZ((uint32_t)(row * 128 + ch * 16));
            const __half* src = (isV ? g_Vh : g_Kh)
                + ((size_t)(b * Ss + s0 + row)) * 768 + h * 64 + ch * 8;
            CP_ASYNC16((isV ? sV : sK) + buf * 8192 + off, src);
        }
        CP_COMMIT();
    };

    float acc[9][4];
    #pragma unroll
    for (int j = 0; j < 9; j++)
        #pragma unroll
        for (int c = 0; c < 4; c++) acc[j][c] = 0.0f;

    // constant fragments
    uint32_t a_ones[4];   // warp 4: A rows 64..79, row 64 = ones
    a_ones[0] = (grp == 0) ? ONES2 : 0u;
    a_ones[1] = 0u;
    a_ones[2] = (grp == 0) ? ONES2 : 0u;
    a_ones[3] = 0u;
    uint32_t b_ones[2];   // n-tile 8: col 64 (n-offset 0) = ones for all k
    b_ones[0] = (grp == 0) ? ONES2 : 0u;
    b_ones[1] = (grp == 0) ? ONES2 : 0u;

    load_tile(0, 0);

    for (int tile = 0; tile < 8; tile++) {
        const int buf = tile & 1;
        if (tile + 1 < 8) {
            load_tile(tile + 1, buf ^ 1);
            asm volatile("cp.async.wait_group 1;" ::: "memory");
        } else {
            asm volatile("cp.async.wait_group 0;" ::: "memory");
        }
        __syncthreads();

        const uint32_t Kb = sK + buf * 8192;
        const uint32_t Vb = sV + buf * 8192;

        #pragma unroll
        for (int ks = 0; ks < 4; ks++) {
            uint32_t afr[4];
            if (wid < 4) {
                // A = K^T: m16 tile rows d = 16*wid.., k16 = s
                int row = ks * 16 + ((lane >> 4) << 3) + (lane & 7);
                uint32_t off = (uint32_t)(row * 128 + wid * 32 + ((lane >> 3) & 1) * 16);
                LDMATRIX_X4_T(afr, Kb + SWZ(off));
            } else {
                afr[0] = a_ones[0]; afr[1] = a_ones[1];
                afr[2] = a_ones[2]; afr[3] = a_ones[3];
            }
            uint32_t bfr[4][4];
            #pragma unroll
            for (int bp = 0; bp < 4; bp++) {
                // B = V^T: n16 tile cols e = 16*bp.., k16 = s
                int row = ks * 16 + (((lane >> 3) & 1) << 3) + (lane & 7);
                uint32_t off = (uint32_t)(row * 128 + bp * 32 + (lane >> 4) * 16);
                LDMATRIX_X4_T(bfr[bp], Vb + SWZ(off));
            }
            #pragma unroll
            for (int nt = 0; nt < 8; nt++)
                mma_f16(acc[nt], afr, &bfr[nt >> 1][(nt & 1) * 2]);
            mma_f16(acc[8], afr, b_ones);
        }
        __syncthreads();
    }

    // -------- atomic epilogue --------
    float* kvb = g_red + KV_OFF + bh * 4096;
    if (wid < 4) {
        int d = wid * 16 + grp;
        #pragma unroll
        for (int nt = 0; nt < 8; nt++) {
            int e = nt * 8 + tig * 2;
            atomicAdd(&kvb[d * 64 + e],           acc[nt][0]);
            atomicAdd(&kvb[d * 64 + e + 1],       acc[nt][1]);
            atomicAdd(&kvb[(d + 8) * 64 + e],     acc[nt][2]);
            atomicAdd(&kvb[(d + 8) * 64 + e + 1], acc[nt][3]);
        }
        if (tig == 0) {
            atomicAdd(&g_red[KSUM_OFF + bh * 64 + d],     acc[8][0]);
            atomicAdd(&g_red[KSUM_OFF + bh * 64 + d + 8], acc[8][2]);
        }
    } else if (grp == 0) {
        #pragma unroll
        for (int nt = 0; nt < 8; nt++) {
            int e = nt * 8 + tig * 2;
            atomicAdd(&g_red[VSUM_OFF + bh * 64 + e],     acc[nt][0]);
            atomicAdd(&g_red[VSUM_OFF + bh * 64 + e + 1], acc[nt][1]);
        }
    }
}

// ---------------- K4: out via fp16 HMMA ---------------------------------------
// C[128 s][80] = Q[128][64] @ kvT^T; kvT[n][k]: n<64 -> kv[k][n], n==64 -> ksum[k],
// n>64 -> 0. out[s][e] = (C[s][e] + vsum[e]) / (C[s][64] + msum + eps).
__global__ void __launch_bounds__(128) out_mma(float* __restrict__ out) {
    __shared__ __half Qs[128 * 64];       // swizzled, 128B rows
    __shared__ __half kvT[80 * 64];       // swizzled, 128B rows
    __shared__ float nqs[128];
    __shared__ float vsm[64];

    const int bh = blockIdx.x, st = blockIdx.y;
    const int b = bh / NH, h = bh % NH;
    const int t = threadIdx.x;
    const int wid = t >> 5, lane = t & 31;
    const int grp = lane >> 2, tig = lane & 3;
    const uint32_t sQ = smem_u32(Qs);
    const uint32_t sT = smem_u32(kvT);

    #pragma unroll
    for (int i = 0; i < 8; i++) {
        int s = t + i * 128;              // 0..1023
        int row = s >> 3, ch = s & 7;
        CP_ASYNC16(sQ + SWZ((uint32_t)(row * 128 + ch * 16)),
                   g_Qh + ((size_t)(b * Ss + st * 128 + row)) * 768 + h * 64 + ch * 8);
    }
    CP_COMMIT();

    // build kvT in fp16 (transposed read of kv; rows 65-79 zero)
    for (int idx = t; idx < 80 * 64; idx += 128) {
        int n = idx >> 6, k = idx & 63;
        float v;
        if (n < 64)       v = g_red[KV_OFF + bh * 4096 + k * 64 + n];
        else if (n == 64) v = g_red[KSUM_OFF + bh * 64 + k];
        else              v = 0.0f;
        *(__half*)((char*)kvT + SWZ((uint32_t)(n * 128 + k * 2))) = __float2half_rn(v);
    }
    if (t < 64) vsm[t] = g_red[VSUM_OFF + bh * 64 + t];
    const float msum = g_red[MSUM_OFF + b];

    asm volatile("cp.async.wait_group 0;" ::: "memory");
    __syncthreads();

    float acc[2][9][4];
    #pragma unroll
    for (int i = 0; i < 2; i++)
        #pragma unroll
        for (int j = 0; j < 9; j++)
            #pragma unroll
            for (int c = 0; c < 4; c++) acc[i][j][c] = 0.0f;

    #pragma unroll
    for (int ks = 0; ks < 4; ks++) {
        const int k0b = ks * 32;
        uint32_t afr[2][4];
        #pragma unroll
        for (int mt = 0; mt < 2; mt++) {
            int row = wid * 32 + mt * 16 + (lane & 15);
            LDMATRIX_X4(afr[mt], sQ + SWZ((uint32_t)(row * 128 + k0b + (lane >> 4) * 16)));
        }
        uint32_t bfr[5][4];
        #pragma unroll
        for (int bp = 0; bp < 5; bp++) {
            int row = bp * 16 + (lane & 7) + ((lane >> 4) << 3);
            LDMATRIX_X4(bfr[bp], sT + SWZ((uint32_t)(row * 128 + k0b + ((lane >> 3) & 1) * 16)));
        }
        #pragma unroll
        for (int mt = 0; mt < 2; mt++)
            #pragma unroll
            for (int nt = 0; nt < 9; nt++)
                mma_f16(acc[mt][nt], afr[mt], &bfr[nt >> 1][(nt & 1) * 2]);
    }

    if (tig == 0) {
        #pragma unroll
        for (int mt = 0; mt < 2; mt++) {
            nqs[wid * 32 + mt * 16 + grp]     = acc[mt][8][0];
            nqs[wid * 32 + mt * 16 + grp + 8] = acc[mt][8][2];
        }
    }
    __syncthreads();

    #pragma unroll
    for (int mt = 0; mt < 2; mt++) {
        int r0 = wid * 32 + mt * 16 + grp;
        float inv0 = 1.0f / (nqs[r0]     + EPS + msum);
        float inv1 = 1.0f / (nqs[r0 + 8] + EPS + msum);
        size_t g0 = ((size_t)(b * Ss + st * 128 + r0))     * HID + h * HD;
        size_t g1 = ((size_t)(b * Ss + st * 128 + r0 + 8)) * HID + h * HD;
        #pragma unroll
        for (int nt = 0; nt < 8; nt++) {
            int col = nt * 8 + tig * 2;
            float vx = vsm[col], vy = vsm[col + 1];
            float2 o0 = make_float2((acc[mt][nt][0] + vx) * inv0, (acc[mt][nt][1] + vy) * inv0);
            float2 o1 = make_float2((acc[mt][nt][2] + vx) * inv1, (acc[mt][nt][3] + vy) * inv1);
            *(float2*)&out[g0 + col] = o0;
            *(float2*)&out[g1 + col] = o1;
        }
    }
}

// ---------------- launch ------------------------------------------------------
extern "C" void kernel_launch(void* const* d_in, const int* in_sizes, int n_in,
                              void* d_out, int out_size)
{
    const float* X  = (const float*)d_in[0];
    const float* am = (const float*)d_in[1];
    const float* Wq = (const float*)d_in[2];
    const float* bq = (const float*)d_in[3];
    const float* Wk = (const float*)d_in[4];
    const float* bk = (const float*)d_in[5];
    const float* Wv = (const float*)d_in[6];
    const float* bv = (const float*)d_in[7];
    float* out = (float*)d_out;

    cudaFuncSetAttribute(gemm_qkv_h, cudaFuncAttributeMaxDynamicSharedMemorySize, GK_SMEM);

    zero_kernel<<<(RED_TOTAL + 255) / 256, 256>>>();
    msum_kernel<<<Bb, 256>>>(am);

    convX_kernel<<<(ROWS * HID / 4) / 256, 256>>>(X);
    convW_kernel<<<(3 * HID * HID / 4) / 256, 256>>>(Wq, Wk, Wv);

    dim3 g1(18, 256);
    gemm_qkv_h<<<g1, 256, GK_SMEM>>>(am, bq, bk, bv);

    dim3 g3(48, 16);
    kv_mma<<<g3, 160>>>();

    dim3 g4(48, 64);
    out_mma<<<g4, 128>>>(out);
}

// round 7
// speedup vs baseline: 7.2640x; 1.0482x over previous
#include <cuda_runtime.h>
#include <cuda_fp16.h>
#include <cstdint>

// Problem constants
#define Bb   4
#define Ss   8192
#define HID  768
#define NH   12
#define HD   64
#define ROWS (Bb*Ss)          // 32768
#define EPS  1e-5f

// ---------------- scratch (device globals; no allocations allowed) ----------
__device__ __half g_Qh[(size_t)ROWS * HID];
__device__ __half g_Kh[(size_t)ROWS * HID];
__device__ __half g_Vh[(size_t)ROWS * HID];
__device__ __half g_Xh[(size_t)ROWS * HID];          // fp16 copy of X
__device__ __half g_Wh[(size_t)3 * HID * HID];       // fp16 [Wq;Wk;Wv]

#define KV_OFF   0                       // 48 * 64 * 64
#define KSUM_OFF (48*4096)               // 48 * 64
#define VSUM_OFF (KSUM_OFF + 48*64)
#define MSUM_OFF (VSUM_OFF + 48*64)
#define RED_TOTAL (MSUM_OFF + 4)
__device__ float g_red[RED_TOTAL];

// ---------------- K0: zero the reduction scratch ----------------------------
__global__ void zero_kernel() {
    int i = blockIdx.x * 256 + threadIdx.x;
    if (i < RED_TOTAL) g_red[i] = 0.0f;
}

// ================= helpers ====================================================
__device__ __forceinline__ uint32_t smem_u32(const void* p) {
    uint32_t a;
    asm("{ .reg .u64 t; cvta.to.shared.u64 t, %1; cvt.u32.u64 %0, t; }" : "=r"(a) : "l"(p));
    return a;
}
#define CP_ASYNC16(dst, src) \
    asm volatile("cp.async.cg.shared.global [%0], [%1], 16;" :: "r"((uint32_t)(dst)), "l"(src) : "memory")
#define CP_COMMIT() asm volatile("cp.async.commit_group;" ::: "memory")
#define SWZ(o) ((o) ^ (((o) >> 3) & 0x70))

__device__ __forceinline__ void mma_f16(float* d, const uint32_t* a, const uint32_t* b) {
    asm volatile(
        "mma.sync.aligned.m16n8k16.row.col.f32.f16.f16.f32 "
        "{%0,%1,%2,%3}, {%4,%5,%6,%7}, {%8,%9}, {%0,%1,%2,%3};"
        : "+f"(d[0]), "+f"(d[1]), "+f"(d[2]), "+f"(d[3])
        : "r"(a[0]), "r"(a[1]), "r"(a[2]), "r"(a[3]), "r"(b[0]), "r"(b[1]));
}
#define LDMATRIX_X4(r, addr) \
    asm volatile("ldmatrix.sync.aligned.m8n8.x4.shared.b16 {%0,%1,%2,%3}, [%4];" \
        : "=r"((r)[0]), "=r"((r)[1]), "=r"((r)[2]), "=r"((r)[3]) : "r"(addr))
#define LDMATRIX_X4_T(r, addr) \
    asm volatile("ldmatrix.sync.aligned.m8n8.x4.trans.shared.b16 {%0,%1,%2,%3}, [%4];" \
        : "=r"((r)[0]), "=r"((r)[1]), "=r"((r)[2]), "=r"((r)[3]) : "r"(addr))
#define ONES2 0x3C003C00u   // half2(1.0, 1.0)

// ---------------- K-1: fp32 -> fp16 converters --------------------------------
__global__ void convX_kernel(const float* __restrict__ X) {
    size_t i = (size_t)blockIdx.x * 256 + threadIdx.x;
    float4 v = ((const float4*)X)[i];
    ((__half2*)g_Xh)[2*i]   = __floats2half2_rn(v.x, v.y);
    ((__half2*)g_Xh)[2*i+1] = __floats2half2_rn(v.z, v.w);
}
__global__ void convW_kernel(const float* __restrict__ Wq,
                             const float* __restrict__ Wk,
                             const float* __restrict__ Wv) {
    size_t i = (size_t)blockIdx.x * 256 + threadIdx.x;
    const size_t per = (size_t)HID * HID / 4;
    const float* src = (i < per) ? Wq : (i < 2*per) ? Wk : Wv;
    size_t j = i % per;
    float4 v = ((const float4*)src)[j];
    ((__half2*)g_Wh)[2*i]   = __floats2half2_rn(v.x, v.y);
    ((__half2*)g_Wh)[2*i+1] = __floats2half2_rn(v.z, v.w);
}

// ---------------- K1: fused QKV projection (fp16 HMMA) + mask + L2-norm -------
// C = X[32768,768] @ W^T. CTA tile 128x128x64, 4 warps (2m x 2n), warp 64x64.
// 3 smem buffers, lookahead-1 cp.async, ONE __syncthreads per k-chunk.
// Each warp's 64 output cols = exactly one head -> warp-local mask+L2 norm.
#define GK_SMEM (6 * 16384)    // A 3x16KB + B 3x16KB

__global__ void __launch_bounds__(128, 2) gemm_qkv_h(
    const float* __restrict__ am,
    const float* __restrict__ bq, const float* __restrict__ bk, const float* __restrict__ bv)
{
    extern __shared__ char smem[];
    const uint32_t sb = smem_u32(smem);

    const int t    = threadIdx.x;
    const int wid  = t >> 5, lane = t & 31;
    const int wm   = wid & 1;           // 2 warps in m
    const int wn   = wid >> 1;          // 2 warps in n
    const int grp  = lane >> 2, tig = lane & 3;

    const int nb = blockIdx.x;          // 0..17
    const int mb = blockIdx.y;          // 0..255
    const int mat = nb / 6;             // 0=q 1=k 2=v
    const float* bias = (mat == 0) ? bq : (mat == 1) ? bk : bv;
    __half* C         = (mat == 0) ? g_Qh : (mat == 1) ? g_Kh : g_Vh;
    const int n0 = (nb % 6) * 128;
    const int m0 = mb * 128;

    const __half* Asrc = g_Xh + (size_t)m0 * 768;
    const __half* Bsrc = g_Wh + (size_t)nb * 128 * 768;

    auto load_tile = [&](int kt, int stg) {
        uint32_t Ad = sb + stg * 16384;
        uint32_t Bd = sb + 49152 + stg * 16384;
        #pragma unroll
        for (int i = 0; i < 8; i++) {
            int s   = t + i * 128;          // 0..1023
            int row = s >> 3, ch = s & 7;
            uint32_t off = SWZ((uint32_t)(row * 128 + ch * 16));
            CP_ASYNC16(Ad + off, Asrc + (size_t)row * 768 + kt * 64 + ch * 8);
            CP_ASYNC16(Bd + off, Bsrc + (size_t)row * 768 + kt * 64 + ch * 8);
        }
        CP_COMMIT();
    };

    float acc[4][8][4];
    #pragma unroll
    for (int i = 0; i < 4; i++)
        #pragma unroll
        for (int j = 0; j < 8; j++)
            #pragma unroll
            for (int c = 0; c < 4; c++) acc[i][j][c] = 0.0f;

    load_tile(0, 0);

    for (int kt = 0; kt < 12; kt++) {
        const int buf = kt % 3;
        if (kt + 1 < 12) {
            load_tile(kt + 1, (kt + 1) % 3);
            asm volatile("cp.async.wait_group 1;" ::: "memory");
        } else {
            asm volatile("cp.async.wait_group 0;" ::: "memory");
        }
        __syncthreads();
        // NOTE: no trailing sync. Next iteration's load targets buffer
        // (kt+2)%3, last read at compute(kt-1), which all warps passed
        // before this iteration's __syncthreads.

        const uint32_t Abase = sb + buf * 16384;
        const uint32_t Bbase = sb + 49152 + buf * 16384;

        #pragma unroll
        for (int ks = 0; ks < 4; ks++) {
            const int k0b = ks * 32;
            uint32_t afr[4][4];
            #pragma unroll
            for (int mt = 0; mt < 4; mt++) {
                int row = wm * 64 + mt * 16 + (lane & 15);
                LDMATRIX_X4(afr[mt], Abase + SWZ((uint32_t)(row * 128 + k0b + (lane >> 4) * 16)));
            }
            uint32_t bfr[4][4];
            #pragma unroll
            for (int bp = 0; bp < 4; bp++) {
                int row = wn * 64 + bp * 16 + (lane & 7) + ((lane >> 4) << 3);
                LDMATRIX_X4(bfr[bp], Bbase + SWZ((uint32_t)(row * 128 + k0b + ((lane >> 3) & 1) * 16)));
            }
            #pragma unroll
            for (int mt = 0; mt < 4; mt++)
                #pragma unroll
                for (int nt = 0; nt < 8; nt++)
                    mma_f16(acc[mt][nt], afr[mt], &bfr[nt >> 1][(nt & 1) * 2]);
        }
    }

    // -------- epilogue (warp-local: this warp's 64 cols = one head) --------
    const int colbase = n0 + wn * 64;
    float bx[8], by[8];
    #pragma unroll
    for (int nt = 0; nt < 8; nt++) {
        bx[nt] = bias[colbase + nt * 8 + tig * 2];
        by[nt] = bias[colbase + nt * 8 + tig * 2 + 1];
    }

    if (mat < 2) {
        #pragma unroll
        for (int mt = 0; mt < 4; mt++) {
            const int r0 = m0 + wm * 64 + mt * 16 + grp;
            const float mr0 = (am[r0]     != 0.0f) ? 0.0f : 1.0f;
            const float mr1 = (am[r0 + 8] != 0.0f) ? 0.0f : 1.0f;
            float ssq0 = 0.0f, ssq1 = 0.0f;
            #pragma unroll
            for (int nt = 0; nt < 8; nt++) {
                float a0 = (acc[mt][nt][0] + bx[nt]) * mr0;
                float a1 = (acc[mt][nt][1] + by[nt]) * mr0;
                float a2 = (acc[mt][nt][2] + bx[nt]) * mr1;
                float a3 = (acc[mt][nt][3] + by[nt]) * mr1;
                acc[mt][nt][0] = a0; acc[mt][nt][1] = a1;
                acc[mt][nt][2] = a2; acc[mt][nt][3] = a3;
                ssq0 += a0*a0 + a1*a1;
                ssq1 += a2*a2 + a3*a3;
            }
            #pragma unroll
            for (int off = 1; off <= 2; off <<= 1) {
                ssq0 += __shfl_xor_sync(0xffffffffu, ssq0, off);
                ssq1 += __shfl_xor_sync(0xffffffffu, ssq1, off);
            }
            const float inv0 = 1.0f / (sqrtf(ssq0) + EPS);
            const float inv1 = 1.0f / (sqrtf(ssq1) + EPS);
            #pragma unroll
            for (int nt = 0; nt < 8; nt++) {
                size_t gc = (size_t)r0 * 768 + colbase + nt * 8 + tig * 2;
                *(__half2*)&C[gc]           = __floats2half2_rn(acc[mt][nt][0] * inv0, acc[mt][nt][1] * inv0);
                *(__half2*)&C[gc + 8 * 768] = __floats2half2_rn(acc[mt][nt][2] * inv1, acc[mt][nt][3] * inv1);
            }
        }
    } else {
        #pragma unroll
        for (int mt = 0; mt < 4; mt++) {
            const int r0 = m0 + wm * 64 + mt * 16 + grp;
            #pragma unroll
            for (int nt = 0; nt < 8; nt++) {
                size_t gc = (size_t)r0 * 768 + colbase + nt * 8 + tig * 2;
                *(__half2*)&C[gc]           = __floats2half2_rn(acc[mt][nt][0] + bx[nt], acc[mt][nt][1] + by[nt]);
                *(__half2*)&C[gc + 8 * 768] = __floats2half2_rn(acc[mt][nt][2] + bx[nt], acc[mt][nt][3] + by[nt]);
            }
        }
    }
}

// ---------------- K2b: msum per batch ----------------------------------------
__global__ void msum_kernel(const float* __restrict__ am) {
    __shared__ float red[256];
    int b = blockIdx.x;
    float s = 0.0f;
    for (int i = threadIdx.x; i < Ss; i += 256)
        s += (am[b * Ss + i] != 0.0f) ? 0.0f : 1.0f;
    red[threadIdx.x] = s;
    __syncthreads();
    for (int o = 128; o; o >>= 1) {
        if (threadIdx.x < o) red[threadIdx.x] += red[threadIdx.x + o];
        __syncthreads();
    }
    if (threadIdx.x == 0) g_red[MSUM_OFF + b] = red[0];
}

// ---------------- K3: kv = K^T V (+ ksum, vsum) via HMMA ----------------------
__global__ void __launch_bounds__(160) kv_mma() {
    __shared__ __half Ks[2][64 * 64];
    __shared__ __half Vs[2][64 * 64];

    const int bh = blockIdx.x, sc = blockIdx.y;
    const int b = bh / NH, h = bh % NH;
    const int t = threadIdx.x;
    const int wid = t >> 5, lane = t & 31;
    const int grp = lane >> 2, tig = lane & 3;
    const uint32_t sK = smem_u32(Ks);
    const uint32_t sV = smem_u32(Vs);
    const int s_base = sc * 512;

    auto load_tile = [&](int tile, int buf) {
        int s0 = s_base + tile * 64;
        for (int i = t; i < 1024; i += 160) {
            int isV = i >> 9;
            int j = i & 511;
            int row = j >> 3, ch = j & 7;
            uint32_t off = SWZ((uint32_t)(row * 128 + ch * 16));
            const __half* src = (isV ? g_Vh : g_Kh)
                + ((size_t)(b * Ss + s0 + row)) * 768 + h * 64 + ch * 8;
            CP_ASYNC16((isV ? sV : sK) + buf * 8192 + off, src);
        }
        CP_COMMIT();
    };

    float acc[9][4];
    #pragma unroll
    for (int j = 0; j < 9; j++)
        #pragma unroll
        for (int c = 0; c < 4; c++) acc[j][c] = 0.0f;

    uint32_t a_ones[4];
    a_ones[0] = (grp == 0) ? ONES2 : 0u;
    a_ones[1] = 0u;
    a_ones[2] = (grp == 0) ? ONES2 : 0u;
    a_ones[3] = 0u;
    uint32_t b_ones[2];
    b_ones[0] = (grp == 0) ? ONES2 : 0u;
    b_ones[1] = (grp == 0) ? ONES2 : 0u;

    load_tile(0, 0);

    for (int tile = 0; tile < 8; tile++) {
        const int buf = tile & 1;
        if (tile + 1 < 8) {
            load_tile(tile + 1, buf ^ 1);
            asm volatile("cp.async.wait_group 1;" ::: "memory");
        } else {
            asm volatile("cp.async.wait_group 0;" ::: "memory");
        }
        __syncthreads();

        const uint32_t Kb = sK + buf * 8192;
        const uint32_t Vb = sV + buf * 8192;

        #pragma unroll
        for (int ks = 0; ks < 4; ks++) {
            uint32_t afr[4];
            if (wid < 4) {
                int row = ks * 16 + ((lane >> 4) << 3) + (lane & 7);
                LDMATRIX_X4_T(afr, Kb + SWZ((uint32_t)(row * 128 + wid * 32 + ((lane >> 3) & 1) * 16)));
            } else {
                afr[0] = a_ones[0]; afr[1] = a_ones[1];
                afr[2] = a_ones[2]; afr[3] = a_ones[3];
            }
            uint32_t bfr[4][4];
            #pragma unroll
            for (int bp = 0; bp < 4; bp++) {
                int row = ks * 16 + (((lane >> 3) & 1) << 3) + (lane & 7);
                LDMATRIX_X4_T(bfr[bp], Vb + SWZ((uint32_t)(row * 128 + bp * 32 + (lane >> 4) * 16)));
            }
            #pragma unroll
            for (int nt = 0; nt < 8; nt++)
                mma_f16(acc[nt], afr, &bfr[nt >> 1][(nt & 1) * 2]);
            mma_f16(acc[8], afr, b_ones);
        }
        __syncthreads();
    }

    float* kvb = g_red + KV_OFF + bh * 4096;
    if (wid < 4) {
        int d = wid * 16 + grp;
        #pragma unroll
        for (int nt = 0; nt < 8; nt++) {
            int e = nt * 8 + tig * 2;
            atomicAdd(&kvb[d * 64 + e],           acc[nt][0]);
            atomicAdd(&kvb[d * 64 + e + 1],       acc[nt][1]);
            atomicAdd(&kvb[(d + 8) * 64 + e],     acc[nt][2]);
            atomicAdd(&kvb[(d + 8) * 64 + e + 1], acc[nt][3]);
        }
        if (tig == 0) {
            atomicAdd(&g_red[KSUM_OFF + bh * 64 + d],     acc[8][0]);
            atomicAdd(&g_red[KSUM_OFF + bh * 64 + d + 8], acc[8][2]);
        }
    } else if (grp == 0) {
        #pragma unroll
        for (int nt = 0; nt < 8; nt++) {
            int e = nt * 8 + tig * 2;
            atomicAdd(&g_red[VSUM_OFF + bh * 64 + e],     acc[nt][0]);
            atomicAdd(&g_red[VSUM_OFF + bh * 64 + e + 1], acc[nt][1]);
        }
    }
}

// ---------------- K4: out via fp16 HMMA ---------------------------------------
__global__ void __launch_bounds__(128) out_mma(float* __restrict__ out) {
    __shared__ __half Qs[128 * 64];
    __shared__ __half kvT[80 * 64];
    __shared__ float nqs[128];
    __shared__ float vsm[64];

    const int bh = blockIdx.x, st = blockIdx.y;
    const int b = bh / NH, h = bh % NH;
    const int t = threadIdx.x;
    const int wid = t >> 5, lane = t & 31;
    const int grp = lane >> 2, tig = lane & 3;
    const uint32_t sQ = smem_u32(Qs);
    const uint32_t sT = smem_u32(kvT);

    #pragma unroll
    for (int i = 0; i < 8; i++) {
        int s = t + i * 128;
        int row = s >> 3, ch = s & 7;
        CP_ASYNC16(sQ + SWZ((uint32_t)(row * 128 + ch * 16)),
                   g_Qh + ((size_t)(b * Ss + st * 128 + row)) * 768 + h * 64 + ch * 8);
    }
    CP_COMMIT();

    for (int idx = t; idx < 80 * 64; idx += 128) {
        int n = idx >> 6, k = idx & 63;
        float v;
        if (n < 64)       v = g_red[KV_OFF + bh * 4096 + k * 64 + n];
        else if (n == 64) v = g_red[KSUM_OFF + bh * 64 + k];
        else              v = 0.0f;
        *(__half*)((char*)kvT + SWZ((uint32_t)(n * 128 + k * 2))) = __float2half_rn(v);
    }
    if (t < 64) vsm[t] = g_red[VSUM_OFF + bh * 64 + t];
    const float msum = g_red[MSUM_OFF + b];

    asm volatile("cp.async.wait_group 0;" ::: "memory");
    __syncthreads();

    float acc[2][9][4];
    #pragma unroll
    for (int i = 0; i < 2; i++)
        #pragma unroll
        for (int j = 0; j < 9; j++)
            #pragma unroll
            for (int c = 0; c < 4; c++) acc[i][j][c] = 0.0f;

    #pragma unroll
    for (int ks = 0; ks < 4; ks++) {
        const int k0b = ks * 32;
        uint32_t afr[2][4];
        #pragma unroll
        for (int mt = 0; mt < 2; mt++) {
            int row = wid * 32 + mt * 16 + (lane & 15);
            LDMATRIX_X4(afr[mt], sQ + SWZ((uint32_t)(row * 128 + k0b + (lane >> 4) * 16)));
        }
        uint32_t bfr[5][4];
        #pragma unroll
        for (int bp = 0; bp < 5; bp++) {
            int row = bp * 16 + (lane & 7) + ((lane >> 4) << 3);
            LDMATRIX_X4(bfr[bp], sT + SWZ((uint32_t)(row * 128 + k0b + ((lane >> 3) & 1) * 16)));
        }
        #pragma unroll
        for (int mt = 0; mt < 2; mt++)
            #pragma unroll
            for (int nt = 0; nt < 9; nt++)
                mma_f16(acc[mt][nt], afr[mt], &bfr[nt >> 1][(nt & 1) * 2]);
    }

    if (tig == 0) {
        #pragma unroll
        for (int mt = 0; mt < 2; mt++) {
            nqs[wid * 32 + mt * 16 + grp]     = acc[mt][8][0];
            nqs[wid * 32 + mt * 16 + grp + 8] = acc[mt][8][2];
        }
    }
    __syncthreads();

    #pragma unroll
    for (int mt = 0; mt < 2; mt++) {
        int r0 = wid * 32 + mt * 16 + grp;
        float inv0 = 1.0f / (nqs[r0]     + EPS + msum);
        float inv1 = 1.0f / (nqs[r0 + 8] + EPS + msum);
        size_t g0 = ((size_t)(b * Ss + st * 128 + r0))     * HID + h * HD;
        size_t g1 = ((size_t)(b * Ss + st * 128 + r0 + 8)) * HID + h * HD;
        #pragma unroll
        for (int nt = 0; nt < 8; nt++) {
            int col = nt * 8 + tig * 2;
            float vx = vsm[col], vy = vsm[col + 1];
            float2 o0 = make_float2((acc[mt][nt][0] + vx) * inv0, (acc[mt][nt][1] + vy) * inv0);
            float2 o1 = make_float2((acc[mt][nt][2] + vx) * inv1, (acc[mt][nt][3] + vy) * inv1);
            *(float2*)&out[g0 + col] = o0;
            *(float2*)&out[g1 + col] = o1;
        }
    }
}

// ---------------- launch ------------------------------------------------------
extern "C" void kernel_launch(void* const* d_in, const int* in_sizes, int n_in,
                              void* d_out, int out_size)
{
    const float* X  = (const float*)d_in[0];
    const float* am = (const float*)d_in[1];
    const float* Wq = (const float*)d_in[2];
    const float* bq = (const float*)d_in[3];
    const float* Wk = (const float*)d_in[4];
    const float* bk = (const float*)d_in[5];
    const float* Wv = (const float*)d_in[6];
    const float* bv = (const float*)d_in[7];
    float* out = (float*)d_out;

    cudaFuncSetAttribute(gemm_qkv_h, cudaFuncAttributeMaxDynamicSharedMemorySize, GK_SMEM);

    zero_kernel<<<(RED_TOTAL + 255) / 256, 256>>>();
    msum_kernel<<<Bb, 256>>>(am);

    convX_kernel<<<(ROWS * HID / 4) / 256, 256>>>(X);
    convW_kernel<<<(3 * HID * HID / 4) / 256, 256>>>(Wq, Wk, Wv);

    dim3 g1(18, 256);
    gemm_qkv_h<<<g1, 128, GK_SMEM>>>(am, bq, bk, bv);

    dim3 g3(48, 16);
    kv_mma<<<g3, 160>>>();

    dim3 g4(48, 64);
    out_mma<<<g4, 128>>>(out);
}